// round 5
// baseline (speedup 1.0000x reference)
#include <cuda_runtime.h>

// ---------------- scratch (device globals; no allocation allowed) ----------------
__device__ float g_a1[2048 * 400 * 32];     // conv1 out [n][p][c]
__device__ float g_a2[2048 * 81 * 64];      // conv2 out [n][p][c]
__device__ float g_a3[2048 * 49 * 64];      // conv3 out [n][p*64+c]
__device__ float g_h[2048 * 512];           // CNN feature
__device__ float g_wfeat[2048 * 32];        // h @ Ww + bw
__device__ float g_hidden[2048 * 8256];     // [map readout 8192 | pos_feat 64]
__device__ float g_w1cat[8256 * 128];       // [wpo1 | wv1]
__device__ float g_part[9 * 2048 * 512];    // split-K partials (sized for FC too)
__device__ float g_z[2048 * 128];           // relu(hidden@W1 + b1)
__device__ float g_w1t[6144];               // conv1 weights [c*64+kykx][oc]
__device__ float g_w2t[32768];              // conv2 weights [ks*32+c][oc]
__device__ float g_w3t[36864];              // conv3 weights [ks*64+c][oc]
__device__ float g_wfcr[3136 * 512];        // wfc re-permuted: [(p*64+c)][nn]
__device__ float g_bcat[128];               // [bpo1 | bv1]

// ---------------- packed f32x2 helpers (B300 FFMA2 path) ----------------
__device__ __forceinline__ void fma2(unsigned long long& d, unsigned long long a,
                                     unsigned long long b) {
    asm("fma.rn.f32x2 %0, %1, %2, %0;" : "+l"(d) : "l"(a), "l"(b));
}
__device__ __forceinline__ unsigned long long pk2(float x) {
    unsigned long long r;
    unsigned u = __float_as_uint(x);
    asm("mov.b64 %0, {%1, %1};" : "=l"(r) : "r"(u));
    return r;
}
__device__ __forceinline__ float2 up2(unsigned long long v) {
    unsigned lo, hi;
    asm("mov.b64 {%0, %1}, %2;" : "=r"(lo), "=r"(hi) : "l"(v));
    return make_float2(__uint_as_float(lo), __uint_as_float(hi));
}

// ---------------- prep: weight transposes / permutes ----------------
__global__ void prep_kernel(const float* __restrict__ w1, const float* __restrict__ w2,
                            const float* __restrict__ w3, const float* __restrict__ wpo1,
                            const float* __restrict__ wv1, const float* __restrict__ wfc,
                            const float* __restrict__ bpo1, const float* __restrict__ bv1) {
    int i = blockIdx.x * blockDim.x + threadIdx.x;
    if (i < 6144) {  // w1 [oc][c][8][8] -> [c*64+kykx][oc]
        int oc = i / 192, r = i - oc * 192;
        g_w1t[r * 32 + oc] = w1[i];
    }
    if (i < 32768) { // w2 [oc][c][4][4] -> [ks*32+c][oc]
        int oc = i >> 9, c = (i >> 4) & 31, kk = i & 15;
        g_w2t[(kk * 32 + c) * 64 + oc] = w2[i];
    }
    if (i < 36864) { // w3 [oc][c][3][3] -> [ks*64+c][oc]
        int oc = i / 576, r = i - oc * 576, c = r / 9, kk = r - c * 9;
        g_w3t[(kk * 64 + c) * 64 + oc] = w3[i];
    }
    if (i < 8256 * 128) {
        int k = i >> 7, nn = i & 127;
        g_w1cat[i] = (nn < 64) ? wpo1[k * 64 + nn] : wv1[k * 64 + nn - 64];
    }
    if (i < 3136 * 512) { // wfc [c*49+p][nn] -> [(p*64+c)][nn]
        int kd = i >> 9, nn = i & 511;
        int p = kd >> 6, c = kd & 63;
        g_wfcr[i] = wfc[(c * 49 + p) * 512 + nn];
    }
    if (i < 128) g_bcat[i] = (i < 64) ? bpo1[i] : bv1[i - 64];
}

// ---------------- conv1: 84x84x3 -> 20x20x32, k=8 s=4, half image per block ----------------
__global__ void __launch_bounds__(256) conv1_kernel(const float* __restrict__ img,
                                                    const float* __restrict__ w1t,
                                                    const float* __restrict__ b1,
                                                    float* __restrict__ out) {
    extern __shared__ float sm[];
    float* s_img = sm;            // 44 rows * 252 = 11088
    float* s_w   = sm + 11088;    // 6144
    const int n = blockIdx.x >> 1, h = blockIdx.x & 1;
    const int tid = threadIdx.x;
    const float4* ip = (const float4*)(img + (size_t)n * 21168 + h * (40 * 252));
    for (int i = tid; i < 2772; i += 256) {
        float4 v = ip[i];
        v.x *= (1.f / 255.f); v.y *= (1.f / 255.f);
        v.z *= (1.f / 255.f); v.w *= (1.f / 255.f);
        ((float4*)s_img)[i] = v;
    }
    for (int i = tid; i < 1536; i += 256) ((float4*)s_w)[i] = ((const float4*)w1t)[i];
    __syncthreads();
    const int ocb = (tid & 3) * 8;
    const int pbase = (tid >> 2) * 4;     // valid < 200
    if (pbase >= 200) return;
    float4 bias0 = *(const float4*)(b1 + ocb);
    float4 bias1 = *(const float4*)(b1 + ocb + 4);
    int oy = pbase / 20, ox0 = pbase - oy * 20;
    int iy0 = oy * 4, ix0 = ox0 * 4;
    unsigned long long acc[4][4];
#pragma unroll
    for (int i = 0; i < 4; ++i)
#pragma unroll
        for (int j = 0; j < 4; ++j) acc[i][j] = 0ull;
    for (int ky = 0; ky < 8; ++ky) {
#pragma unroll
        for (int kx = 0; kx < 8; ++kx) {
            int ib = ((iy0 + ky) * 84 + ix0 + kx) * 3;
            const float* wp = s_w + (ky * 8 + kx) * 32 + ocb;
#pragma unroll
            for (int c = 0; c < 3; ++c) {
                unsigned long long v0 = pk2(s_img[ib + c]);
                unsigned long long v1 = pk2(s_img[ib + 12 + c]);
                unsigned long long v2 = pk2(s_img[ib + 24 + c]);
                unsigned long long v3 = pk2(s_img[ib + 36 + c]);
                const ulonglong2* wq = (const ulonglong2*)(wp + c * 2048);
                ulonglong2 wa = wq[0], wb = wq[1];
                fma2(acc[0][0], v0, wa.x); fma2(acc[0][1], v0, wa.y);
                fma2(acc[0][2], v0, wb.x); fma2(acc[0][3], v0, wb.y);
                fma2(acc[1][0], v1, wa.x); fma2(acc[1][1], v1, wa.y);
                fma2(acc[1][2], v1, wb.x); fma2(acc[1][3], v1, wb.y);
                fma2(acc[2][0], v2, wa.x); fma2(acc[2][1], v2, wa.y);
                fma2(acc[2][2], v2, wb.x); fma2(acc[2][3], v2, wb.y);
                fma2(acc[3][0], v3, wa.x); fma2(acc[3][1], v3, wa.y);
                fma2(acc[3][2], v3, wb.x); fma2(acc[3][3], v3, wb.y);
            }
        }
    }
#pragma unroll
    for (int i = 0; i < 4; ++i) {
        float2 p0 = up2(acc[i][0]), p1 = up2(acc[i][1]);
        float2 p2 = up2(acc[i][2]), p3 = up2(acc[i][3]);
        float4 o0, o1;
        o0.x = fmaxf(p0.x + bias0.x, 0.f); o0.y = fmaxf(p0.y + bias0.y, 0.f);
        o0.z = fmaxf(p1.x + bias0.z, 0.f); o0.w = fmaxf(p1.y + bias0.w, 0.f);
        o1.x = fmaxf(p2.x + bias1.x, 0.f); o1.y = fmaxf(p2.y + bias1.y, 0.f);
        o1.z = fmaxf(p3.x + bias1.z, 0.f); o1.w = fmaxf(p3.y + bias1.w, 0.f);
        float* op = out + ((size_t)n * 400 + h * 200 + pbase + i) * 32 + ocb;
        *(float4*)op = o0;
        *(float4*)(op + 4) = o1;
    }
}

// ---------------- unified GEMM / implicit-im2col conv ----------------
// BM=256, BN=64, BK=16, 256 threads, 8x8 thread tile via FFMA2.
// MODE 0: A direct [M][lda]; MODE 1: conv2 gather; MODE 2: conv3 gather.
// As stored duplicated (v,v): LDS.128 yields ready f32x2 broadcast operands.
template<int MODE>
__global__ void __launch_bounds__(256, 2) gemmA(const float* __restrict__ A, int lda,
                                                const float* __restrict__ B, int ldb,
                                                float* __restrict__ C,
                                                int N, int K, int ksteps, int Mtotal,
                                                const float* __restrict__ bias,
                                                int dorelu) {
    extern __shared__ float sm[];
    float* sA = sm;             // 2 * 16 * 512
    float* sB = sm + 16384;     // 2 * 16 * 64
    const int bm = blockIdx.y * 256, bn = blockIdx.x * 64;
    const int z = blockIdx.z;
    const int kbeg = z * ksteps * 16;
    const int kend = min(K, kbeg + ksteps * 16);
    C += (size_t)z * Mtotal * N;
    const int tid = threadIdx.x;
    // A-load: thread owns one m-row, loads 16 k's per step
    const int gm = bm + tid;
    size_t abase = 0; int oy = 0, ox = 0;
    if (MODE == 0) {
        abase = (size_t)gm * lda;
    } else if (MODE == 1) {
        int n = gm / 81, p = gm - n * 81;
        oy = (p / 9) * 2; ox = (p - (p / 9) * 9) * 2;
        abase = (size_t)n * 12800;
    } else {
        int n = gm / 49, p = gm - n * 49;
        oy = p / 7; ox = p - oy * 7;
        abase = (size_t)n * 5184;
    }
    const int brow = tid >> 4, bcol = (tid & 15) * 4;
    const int tr = tid >> 3, tc = tid & 7;

    unsigned long long acc[8][4];
#pragma unroll
    for (int i = 0; i < 8; ++i)
#pragma unroll
        for (int j = 0; j < 4; ++j) acc[i][j] = 0ull;

    auto ldA = [&](int k0, float4* x) {
        const float* p;
        if (MODE == 0) {
            p = A + abase + k0;
        } else if (MODE == 1) {
            int ks = k0 >> 5;                 // 16 consecutive k stay in one pixel
            int ky = ks >> 2, kx = ks & 3;
            p = A + abase + ((oy + ky) * 20 + ox + kx) * 32 + (k0 & 31);
        } else {
            int ks = k0 >> 6;
            int ky = ks / 3, kx = ks - ky * 3;
            p = A + abase + ((oy + ky) * 9 + ox + kx) * 64 + (k0 & 63);
        }
        x[0] = *(const float4*)p;
        x[1] = *(const float4*)(p + 4);
        x[2] = *(const float4*)(p + 8);
        x[3] = *(const float4*)(p + 12);
    };
    auto stA = [&](int buf, const float4* x) {
        float* d = sA + buf * 8192 + 2 * tid;
#pragma unroll
        for (int q = 0; q < 4; ++q) {
            *(float2*)(d + (q * 4 + 0) * 512) = make_float2(x[q].x, x[q].x);
            *(float2*)(d + (q * 4 + 1) * 512) = make_float2(x[q].y, x[q].y);
            *(float2*)(d + (q * 4 + 2) * 512) = make_float2(x[q].z, x[q].z);
            *(float2*)(d + (q * 4 + 3) * 512) = make_float2(x[q].w, x[q].w);
        }
    };

    float4 ax[4], rb;
    ldA(kbeg, ax);
    rb = *(const float4*)(B + (size_t)(kbeg + brow) * ldb + bn + bcol);
    stA(0, ax);
    *(float4*)(sB + 0 * 1024 + brow * 64 + bcol) = rb;
    __syncthreads();

    int cur = 0;
    for (int k0 = kbeg; k0 < kend; k0 += 16) {
        bool more = (k0 + 16) < kend;
        if (more) {
            ldA(k0 + 16, ax);
            rb = *(const float4*)(B + (size_t)(k0 + 16 + brow) * ldb + bn + bcol);
        }
        const float* Abuf = sA + cur * 8192;
        const float* Bbuf = sB + cur * 1024;
#pragma unroll
        for (int kk = 0; kk < 16; ++kk) {
            const ulonglong2* ap = (const ulonglong2*)(Abuf + kk * 512 + tr * 16);
            ulonglong2 A0 = ap[0], A1 = ap[1], A2 = ap[2], A3 = ap[3];
            const ulonglong2* bp = (const ulonglong2*)(Bbuf + kk * 64 + tc * 8);
            ulonglong2 B0 = bp[0], B1 = bp[1];
            unsigned long long ar[8] = {A0.x, A0.y, A1.x, A1.y, A2.x, A2.y, A3.x, A3.y};
#pragma unroll
            for (int i = 0; i < 8; ++i) {
                fma2(acc[i][0], ar[i], B0.x);
                fma2(acc[i][1], ar[i], B0.y);
                fma2(acc[i][2], ar[i], B1.x);
                fma2(acc[i][3], ar[i], B1.y);
            }
        }
        if (more) {
            stA(cur ^ 1, ax);
            *(float4*)(sB + (cur ^ 1) * 1024 + brow * 64 + bcol) = rb;
        }
        __syncthreads();
        cur ^= 1;
    }

    float4 bb0 = make_float4(0.f, 0.f, 0.f, 0.f), bb1 = bb0;
    if (bias) {
        bb0 = *(const float4*)(bias + bn + tc * 8);
        bb1 = *(const float4*)(bias + bn + tc * 8 + 4);
    }
#pragma unroll
    for (int i = 0; i < 8; ++i) {
        int m = bm + tr * 8 + i;
        float2 p0 = up2(acc[i][0]), p1 = up2(acc[i][1]);
        float2 p2 = up2(acc[i][2]), p3 = up2(acc[i][3]);
        float4 o0, o1;
        o0.x = p0.x + bb0.x; o0.y = p0.y + bb0.y; o0.z = p1.x + bb0.z; o0.w = p1.y + bb0.w;
        o1.x = p2.x + bb1.x; o1.y = p2.y + bb1.y; o1.z = p3.x + bb1.z; o1.w = p3.y + bb1.w;
        if (dorelu) {
            o0.x = fmaxf(o0.x, 0.f); o0.y = fmaxf(o0.y, 0.f);
            o0.z = fmaxf(o0.z, 0.f); o0.w = fmaxf(o0.w, 0.f);
            o1.x = fmaxf(o1.x, 0.f); o1.y = fmaxf(o1.y, 0.f);
            o1.z = fmaxf(o1.z, 0.f); o1.w = fmaxf(o1.w, 0.f);
        }
        float* cp = &C[(size_t)m * N + bn + tc * 8];
        *(float4*)cp = o0;
        *(float4*)(cp + 4) = o1;
    }
}

// ---------------- generic split-K reduce + bias + relu ----------------
__global__ void reduce_kernel(const float* __restrict__ bias, float* __restrict__ outp,
                              int N, int nparts, int stride, int count, int dorelu) {
    int i = blockIdx.x * blockDim.x + threadIdx.x;
    if (i >= count) return;
    float s = 0.f;
    for (int ss = 0; ss < nparts; ++ss) s += g_part[(size_t)ss * stride + i];
    s += bias[i % N];
    outp[i] = dorelu ? fmaxf(s, 0.f) : s;
}

// ---------------- wfeat = g_h @ Ww + bw  (2048 x 32, K=512) ----------------
__global__ void __launch_bounds__(256) wfeat_kernel(const float* __restrict__ Ww,
                                                    const float* __restrict__ bw) {
    int t = blockIdx.x * 256 + threadIdx.x;   // 65536
    int n = t >> 5, oc = t & 31;
    const float* hrow = g_h + (size_t)n * 512;
    float s = bw[oc];
#pragma unroll 8
    for (int k = 0; k < 512; ++k) s += hrow[k] * Ww[k * 32 + oc];
    g_wfeat[t] = s;
}

// ---------------- sequential scan; state in registers; channel split ----------------
__global__ void __launch_bounds__(256) scan_kernel(const float* __restrict__ done,
                                                   const float* __restrict__ state0,
                                                   const int* __restrict__ position,
                                                   float* __restrict__ out_state) {
    const int b = blockIdx.x, cq = blockIdx.y * 8, j = threadIdx.x;
    float st[8];
#pragma unroll
    for (int c = 0; c < 8; ++c) st[c] = state0[b * 8192 + (cq + c) * 256 + j];
    for (int t = 0; t < 32; ++t) {
        int idx = t * 64 + b;
        float m = 1.0f - done[idx];
#pragma unroll
        for (int c = 0; c < 8; ++c) st[c] *= m;
        int p0 = position[idx * 2], p1 = position[idx * 2 + 1];
        if (j == p0 * 16 + p1) {
#pragma unroll
            for (int c = 0; c < 8; ++c) st[c] += g_wfeat[idx * 32 + cq + c];
        }
        float* hrow = g_hidden + (size_t)idx * 8256;
#pragma unroll
        for (int c = 0; c < 8; ++c) hrow[(cq + c) * 256 + j] = st[c];
    }
#pragma unroll
    for (int c = 0; c < 8; ++c) out_state[b * 8192 + (cq + c) * 256 + j] = st[c];
}

// ---------------- pos_net: one-hot MLP -> hidden cols 8192..8255 ----------------
__global__ void __launch_bounds__(64) posnet_kernel(const int* __restrict__ position,
                                                    const float* __restrict__ wp1,
                                                    const float* __restrict__ bp1,
                                                    const float* __restrict__ wp2,
                                                    const float* __restrict__ bp2) {
    __shared__ float hr[64];
    const int n = blockIdx.x, k = threadIdx.x;
    int p0 = position[n * 2], p1 = position[n * 2 + 1];
    hr[k] = fmaxf(wp1[p0 * 64 + k] + wp1[(16 + p1) * 64 + k] + bp1[k], 0.f);
    __syncthreads();
    float s = bp2[k];
#pragma unroll 8
    for (int j = 0; j < 64; ++j) s += hr[j] * wp2[j * 64 + k];
    g_hidden[(size_t)n * 8256 + 8192 + k] = s;
}

// ---------------- heads: logits + value ----------------
__global__ void heads_kernel(const float* __restrict__ wpo2, const float* __restrict__ bpo2,
                             const float* __restrict__ wv2, const float* __restrict__ bv2,
                             float* __restrict__ out_logits, float* __restrict__ out_v) {
    int n = blockIdx.x * blockDim.x + threadIdx.x;
    if (n >= 2048) return;
    const float* z = g_z + (size_t)n * 128;
    float lg[5];
#pragma unroll
    for (int a = 0; a < 5; ++a) lg[a] = bpo2[a];
    float vv = bv2[0];
#pragma unroll 4
    for (int j = 0; j < 64; ++j) {
        float zj = z[j];
#pragma unroll
        for (int a = 0; a < 5; ++a) lg[a] += zj * wpo2[j * 5 + a];
        vv += z[64 + j] * wv2[j];
    }
#pragma unroll
    for (int a = 0; a < 5; ++a) out_logits[n * 5 + a] = lg[a];
    out_v[n] = vv;
}

// ---------------- launch ----------------
extern "C" void kernel_launch(void* const* d_in, const int* in_sizes, int n_in,
                              void* d_out, int out_size) {
    bool dict_order = (in_sizes[3] == 4096 && in_sizes[4] == 6144);
    int wb = dict_order ? 4 : 3;
    int posIdx = dict_order ? 3 : 25;

    const float* image  = (const float*)d_in[0];
    const float* done   = (const float*)d_in[1];
    const float* state0 = (const float*)d_in[2];
    const int*   position = (const int*)d_in[posIdx];
    const float* w1  = (const float*)d_in[wb + 0];
    const float* b1  = (const float*)d_in[wb + 1];
    const float* w2  = (const float*)d_in[wb + 2];
    const float* b2  = (const float*)d_in[wb + 3];
    const float* w3  = (const float*)d_in[wb + 4];
    const float* b3  = (const float*)d_in[wb + 5];
    const float* wfc = (const float*)d_in[wb + 6];
    const float* bfc = (const float*)d_in[wb + 7];
    const float* Ww  = (const float*)d_in[wb + 8];
    const float* bw  = (const float*)d_in[wb + 9];
    const float* wp1 = (const float*)d_in[wb + 10];
    const float* bp1 = (const float*)d_in[wb + 11];
    const float* wp2 = (const float*)d_in[wb + 12];
    const float* bp2 = (const float*)d_in[wb + 13];
    const float* wpo1 = (const float*)d_in[wb + 14];
    const float* bpo1 = (const float*)d_in[wb + 15];
    const float* wpo2 = (const float*)d_in[wb + 16];
    const float* bpo2 = (const float*)d_in[wb + 17];
    const float* wv1 = (const float*)d_in[wb + 18];
    const float* bv1 = (const float*)d_in[wb + 19];
    const float* wv2 = (const float*)d_in[wb + 20];
    const float* bv2 = (const float*)d_in[wb + 21];

    float* out = (float*)d_out;
    float* out_logits = out;               // 2048*5
    float* out_v      = out + 10240;       // 2048
    float* out_state  = out + 12288;       // 64*32*16*16

    float *p_a1, *p_a2, *p_a3, *p_h, *p_hidden, *p_w1cat, *p_part;
    float *p_w1t, *p_w2t, *p_w3t, *p_wfcr, *p_bcat, *p_z;
    cudaGetSymbolAddress((void**)&p_a1, g_a1);
    cudaGetSymbolAddress((void**)&p_a2, g_a2);
    cudaGetSymbolAddress((void**)&p_a3, g_a3);
    cudaGetSymbolAddress((void**)&p_h, g_h);
    cudaGetSymbolAddress((void**)&p_hidden, g_hidden);
    cudaGetSymbolAddress((void**)&p_w1cat, g_w1cat);
    cudaGetSymbolAddress((void**)&p_part, g_part);
    cudaGetSymbolAddress((void**)&p_w1t, g_w1t);
    cudaGetSymbolAddress((void**)&p_w2t, g_w2t);
    cudaGetSymbolAddress((void**)&p_w3t, g_w3t);
    cudaGetSymbolAddress((void**)&p_wfcr, g_wfcr);
    cudaGetSymbolAddress((void**)&p_bcat, g_bcat);
    cudaGetSymbolAddress((void**)&p_z, g_z);

    const int GEMM_SMEM = 73728;
    cudaFuncSetAttribute(conv1_kernel, cudaFuncAttributeMaxDynamicSharedMemorySize, 68928);
    cudaFuncSetAttribute(gemmA<0>, cudaFuncAttributeMaxDynamicSharedMemorySize, GEMM_SMEM);
    cudaFuncSetAttribute(gemmA<1>, cudaFuncAttributeMaxDynamicSharedMemorySize, GEMM_SMEM);
    cudaFuncSetAttribute(gemmA<2>, cudaFuncAttributeMaxDynamicSharedMemorySize, GEMM_SMEM);

    prep_kernel<<<3137, 512>>>(w1, w2, w3, wpo1, wv1, wfc, bpo1, bv1);
    conv1_kernel<<<4096, 256, 68928>>>(image, p_w1t, b1, p_a1);
    // conv2: M=165888, N=64, K=512
    gemmA<1><<<dim3(1, 648, 1), 256, GEMM_SMEM>>>(p_a1, 0, p_w2t, 64, p_a2,
                                                  64, 512, 32, 165888, b2, 1);
    // conv3: M=100352, N=64, K=576
    gemmA<2><<<dim3(1, 392, 1), 256, GEMM_SMEM>>>(p_a2, 0, p_w3t, 64, p_a3,
                                                  64, 576, 36, 100352, b3, 1);
    // FC: M=2048, N=512, K=3136, split-K=2
    gemmA<0><<<dim3(8, 8, 2), 256, GEMM_SMEM>>>(p_a3, 3136, p_wfcr, 512, p_part,
                                                512, 3136, 98, 2048, (const float*)0, 0);
    reduce_kernel<<<2048, 512>>>(bfc, p_h, 512, 2, 2048 * 512, 2048 * 512, 1);
    wfeat_kernel<<<256, 256>>>(Ww, bw);
    scan_kernel<<<dim3(64, 4, 1), 256>>>(done, state0, position, out_state);
    posnet_kernel<<<2048, 64>>>(position, wp1, bp1, wp2, bp2);
    // policy/value: M=2048, N=128, K=8256, split-K=9
    gemmA<0><<<dim3(2, 8, 9), 256, GEMM_SMEM>>>(p_hidden, 8256, p_w1cat, 128, p_part,
                                                128, 8256, 58, 2048, (const float*)0, 0);
    reduce_kernel<<<512, 512>>>(p_bcat, p_z, 128, 9, 2048 * 128, 2048 * 128, 1);
    heads_kernel<<<16, 128>>>(wpo2, bpo2, wv2, bv2, out_logits, out_v);
}

// round 7
// speedup vs baseline: 1.4912x; 1.4912x over previous
#include <cuda_runtime.h>
#include <cuda_bf16.h>
#include <cstdint>

// ---------------- scratch (device globals; no allocation allowed) ----------------
__device__ float g_a1[2048 * 400 * 32];     // conv1 out [n][p][c]
__device__ float g_a2[2048 * 81 * 64];      // conv2 out [n][p][c]
__device__ float g_a3[2048 * 49 * 64];      // conv3 out [n][p*64+c]
__device__ float g_h[2048 * 512];           // CNN feature
__device__ float g_wfeat[2048 * 32];        // h @ Ww + bw
__device__ float g_hidden[2048 * 8256];     // [map readout 8192 | pos_feat 64]
__device__ float g_part[4 * 2048 * 128];    // split-K partials (policy)
__device__ float g_z[2048 * 128];           // relu(hidden@W1 + b1)
__device__ float g_w1t[6144];               // conv1 weights [c*64+kykx][oc]
__device__ float g_bcat[128];               // [bpo1 | bv1]
// pre-split bf16 hi/lo weight tiles: per chunk 16KB = [hi 8KB: 64n x 64k][lo 8KB]
__device__ uint4 g_w2sw[8 * 1024];          // conv2: 8 chunks
__device__ uint4 g_w3sw[9 * 1024];          // conv3: 9 chunks
__device__ uint4 g_wfcsw[8 * 49 * 1024];    // FC: 8 ntiles x 49 chunks
__device__ uint4 g_wposw[2 * 129 * 1024];   // policy: 2 ntiles x 129 chunks

// ---------------- helpers ----------------
static __device__ __forceinline__ uint32_t s2u(const void* p) {
    uint32_t a;
    asm("{ .reg .u64 t; cvta.to.shared.u64 t, %1; cvt.u32.u64 %0, t; }" : "=r"(a) : "l"(p));
    return a;
}
static __device__ __forceinline__ void ldsm4(uint32_t addr, uint32_t* r) {
    asm volatile("ldmatrix.sync.aligned.m8n8.x4.shared.b16 {%0,%1,%2,%3}, [%4];"
                 : "=r"(r[0]), "=r"(r[1]), "=r"(r[2]), "=r"(r[3]) : "r"(addr));
}
static __device__ __forceinline__ void ldsm2(uint32_t addr, uint32_t* r) {
    asm volatile("ldmatrix.sync.aligned.m8n8.x2.shared.b16 {%0,%1}, [%2];"
                 : "=r"(r[0]), "=r"(r[1]) : "r"(addr));
}
static __device__ __forceinline__ void mma16816(float* c, const uint32_t* a,
                                                const uint32_t* b) {
    asm volatile(
        "mma.sync.aligned.m16n8k16.row.col.f32.bf16.bf16.f32 "
        "{%0,%1,%2,%3}, {%4,%5,%6,%7}, {%8,%9}, {%0,%1,%2,%3};"
        : "+f"(c[0]), "+f"(c[1]), "+f"(c[2]), "+f"(c[3])
        : "r"(a[0]), "r"(a[1]), "r"(a[2]), "r"(a[3]), "r"(b[0]), "r"(b[1]));
}
static __device__ __forceinline__ void cvt8(float4 a, float4 b, uint4& h, uint4& l) {
    float f[8] = {a.x, a.y, a.z, a.w, b.x, b.y, b.z, b.w};
    unsigned hh[4], ll[4];
#pragma unroll
    for (int i = 0; i < 4; ++i) {
        __nv_bfloat16 h0 = __float2bfloat16_rn(f[2 * i]);
        __nv_bfloat16 h1 = __float2bfloat16_rn(f[2 * i + 1]);
        float r0 = f[2 * i] - __bfloat162float(h0);
        float r1 = f[2 * i + 1] - __bfloat162float(h1);
        __nv_bfloat16 l0 = __float2bfloat16_rn(r0);
        __nv_bfloat16 l1 = __float2bfloat16_rn(r1);
        hh[i] = (unsigned)__bfloat16_as_ushort(h0) | ((unsigned)__bfloat16_as_ushort(h1) << 16);
        ll[i] = (unsigned)__bfloat16_as_ushort(l0) | ((unsigned)__bfloat16_as_ushort(l1) << 16);
    }
    h = make_uint4(hh[0], hh[1], hh[2], hh[3]);
    l = make_uint4(ll[0], ll[1], ll[2], ll[3]);
}

// ---------------- prep: weight split + pack into [n][k] hi/lo tiles ----------------
static __device__ __forceinline__ void wsplit_store(uint4* dst_tiles, int tile, int nn,
                                                    int kk, float v) {
    __nv_bfloat16 h = __float2bfloat16_rn(v);
    __nv_bfloat16 l = __float2bfloat16_rn(v - __bfloat162float(h));
    char* base = (char*)dst_tiles + (size_t)tile * 16384;
    unsigned off = (unsigned)(nn * 128 + kk * 2);
    *(__nv_bfloat16*)(base + off) = h;
    *(__nv_bfloat16*)(base + 8192 + off) = l;
}

__global__ void prep_kernel(const float* __restrict__ w1, const float* __restrict__ w2,
                            const float* __restrict__ w3, const float* __restrict__ wpo1,
                            const float* __restrict__ wv1, const float* __restrict__ wfc,
                            const float* __restrict__ bpo1, const float* __restrict__ bv1) {
    int i = blockIdx.x * blockDim.x + threadIdx.x;
    if (i < 6144) {  // conv1 (FFMA2 path): [oc][c][8][8] -> [c*64+kykx][oc]
        int oc = i / 192, r = i - oc * 192;
        g_w1t[r * 32 + oc] = w1[i];
    }
    if (i < 32768) { // conv2: w2[oc][c][ky][kx], k = (ky*4+kx)*32+c
        int oc = i >> 9, c = (i >> 4) & 31, ks = i & 15;
        int k = ks * 32 + c;
        wsplit_store(g_w2sw, k >> 6, oc, k & 63, w2[i]);
    }
    if (i < 36864) { // conv3: w3[oc][c][ky][kx], k = (ky*3+kx)*64+c
        int oc = i / 576, r = i - oc * 576, c = r / 9, ks = r - c * 9;
        int k = ks * 64 + c;
        wsplit_store(g_w3sw, k >> 6, oc, k & 63, w3[i]);
    }
    if (i < 8256 * 128) { // policy/value cat: B[n][k] = w1cat[k][n]
        int k = i >> 7, n = i & 127;
        float v = (n < 64) ? wpo1[k * 64 + n] : wv1[k * 64 + n - 64];
        wsplit_store(g_wposw, (n >> 6) * 129 + (k >> 6), n & 63, k & 63, v);
    }
    if (i < 3136 * 512) { // FC: k = p*64+c; src wfc[(c*49+p)][n]
        int k = i >> 9, n = i & 511;
        int p = k >> 6, c = k & 63;
        float v = wfc[(size_t)(c * 49 + p) * 512 + n];
        wsplit_store(g_wfcsw, (n >> 6) * 49 + p, n & 63, c, v);
    }
    if (i < 128) g_bcat[i] = (i < 64) ? bpo1[i] : bv1[i - 64];
}

// ---------------- conv1: 84x84x3 -> 20x20x32, k=8 s=4 (FFMA2) ----------------
__device__ __forceinline__ void fma2(unsigned long long& d, unsigned long long a,
                                     unsigned long long b) {
    asm("fma.rn.f32x2 %0, %1, %2, %0;" : "+l"(d) : "l"(a), "l"(b));
}
__device__ __forceinline__ unsigned long long pk2(float x) {
    unsigned long long r;
    unsigned u = __float_as_uint(x);
    asm("mov.b64 %0, {%1, %1};" : "=l"(r) : "r"(u));
    return r;
}
__device__ __forceinline__ float2 up2(unsigned long long v) {
    unsigned lo, hi;
    asm("mov.b64 {%0, %1}, %2;" : "=r"(lo), "=r"(hi) : "l"(v));
    return make_float2(__uint_as_float(lo), __uint_as_float(hi));
}

__global__ void __launch_bounds__(256) conv1_kernel(const float* __restrict__ img,
                                                    const float* __restrict__ w1t,
                                                    const float* __restrict__ b1,
                                                    float* __restrict__ out) {
    extern __shared__ float sm[];
    float* s_img = sm;            // 44 rows * 252 = 11088
    float* s_w   = sm + 11088;    // 6144
    const int n = blockIdx.x >> 1, h = blockIdx.x & 1;
    const int tid = threadIdx.x;
    const float4* ip = (const float4*)(img + (size_t)n * 21168 + h * (40 * 252));
    for (int i = tid; i < 2772; i += 256) {
        float4 v = ip[i];
        v.x *= (1.f / 255.f); v.y *= (1.f / 255.f);
        v.z *= (1.f / 255.f); v.w *= (1.f / 255.f);
        ((float4*)s_img)[i] = v;
    }
    for (int i = tid; i < 1536; i += 256) ((float4*)s_w)[i] = ((const float4*)w1t)[i];
    __syncthreads();
    const int ocb = (tid & 3) * 8;
    const int pbase = (tid >> 2) * 4;
    if (pbase >= 200) return;
    float4 bias0 = *(const float4*)(b1 + ocb);
    float4 bias1 = *(const float4*)(b1 + ocb + 4);
    int oy = pbase / 20, ox0 = pbase - oy * 20;
    int iy0 = oy * 4, ix0 = ox0 * 4;
    unsigned long long acc[4][4];
#pragma unroll
    for (int i = 0; i < 4; ++i)
#pragma unroll
        for (int j = 0; j < 4; ++j) acc[i][j] = 0ull;
    for (int ky = 0; ky < 8; ++ky) {
#pragma unroll
        for (int kx = 0; kx < 8; ++kx) {
            int ib = ((iy0 + ky) * 84 + ix0 + kx) * 3;
            const float* wp = s_w + (ky * 8 + kx) * 32 + ocb;
#pragma unroll
            for (int c = 0; c < 3; ++c) {
                unsigned long long v0 = pk2(s_img[ib + c]);
                unsigned long long v1 = pk2(s_img[ib + 12 + c]);
                unsigned long long v2 = pk2(s_img[ib + 24 + c]);
                unsigned long long v3 = pk2(s_img[ib + 36 + c]);
                const ulonglong2* wq = (const ulonglong2*)(wp + c * 2048);
                ulonglong2 wa = wq[0], wb = wq[1];
                fma2(acc[0][0], v0, wa.x); fma2(acc[0][1], v0, wa.y);
                fma2(acc[0][2], v0, wb.x); fma2(acc[0][3], v0, wb.y);
                fma2(acc[1][0], v1, wa.x); fma2(acc[1][1], v1, wa.y);
                fma2(acc[1][2], v1, wb.x); fma2(acc[1][3], v1, wb.y);
                fma2(acc[2][0], v2, wa.x); fma2(acc[2][1], v2, wa.y);
                fma2(acc[2][2], v2, wb.x); fma2(acc[2][3], v2, wb.y);
                fma2(acc[3][0], v3, wa.x); fma2(acc[3][1], v3, wa.y);
                fma2(acc[3][2], v3, wb.x); fma2(acc[3][3], v3, wb.y);
            }
        }
    }
#pragma unroll
    for (int i = 0; i < 4; ++i) {
        float2 p0 = up2(acc[i][0]), p1 = up2(acc[i][1]);
        float2 p2 = up2(acc[i][2]), p3 = up2(acc[i][3]);
        float4 o0, o1;
        o0.x = fmaxf(p0.x + bias0.x, 0.f); o0.y = fmaxf(p0.y + bias0.y, 0.f);
        o0.z = fmaxf(p1.x + bias0.z, 0.f); o0.w = fmaxf(p1.y + bias0.w, 0.f);
        o1.x = fmaxf(p2.x + bias1.x, 0.f); o1.y = fmaxf(p2.y + bias1.y, 0.f);
        o1.z = fmaxf(p3.x + bias1.z, 0.f); o1.w = fmaxf(p3.y + bias1.w, 0.f);
        float* op = out + ((size_t)n * 400 + h * 200 + pbase + i) * 32 + ocb;
        *(float4*)op = o0;
        *(float4*)(op + 4) = o1;
    }
}

// ---------------- mma.sync GEMM: 128x64 tile, K chunks of 64, bf16 hi/lo 3-MMA ----
// MODE 0: A direct [gm][lda]; MODE 1: conv2 im2col; MODE 2: conv3 im2col.
// smem (bytes): A_hi[128][72 bf16] @0 (18432), A_lo @18432, B_hi[64][72] @36864
// (9216), B_lo @46080. total 55296.
template<int MODE>
__global__ void __launch_bounds__(256, 2) gemmMM(const float* __restrict__ A, int lda,
                                                 const uint4* __restrict__ Bt,
                                                 float* __restrict__ C, int ldc,
                                                 int qsplit, int qtotal, int Mtotal,
                                                 const float* __restrict__ bias,
                                                 int dorelu) {
    extern __shared__ __align__(16) char smem[];
    const int tid = threadIdx.x;
    const uint32_t sb = s2u(smem);
    const int mtile = blockIdx.y, ntile = blockIdx.x, z = blockIdx.z;
    C += (size_t)z * Mtotal * ldc;

    // ---- A gather mapping (thread = row, half) ----
    const int arow = tid & 127, ahalf = tid >> 7;
    const int gm = mtile * 128 + arow;
    size_t abase = 0; int oy = 0, ox = 0;
    if (MODE == 0) abase = (size_t)gm * lda;
    else if (MODE == 1) { int n = gm / 81, p = gm - n * 81; oy = (p / 9) * 2; ox = (p % 9) * 2; abase = (size_t)n * 12800; }
    else { int n = gm / 49, p = gm - n * 49; oy = p / 7; ox = p - oy * 7; abase = (size_t)n * 5184; }

    // ---- B copy mapping ----
    const int bcrow = tid >> 2, bcseg = tid & 3;

    // ---- fragment address mapping ----
    const int wid = tid >> 5, L = tid & 31;
    const int warpM = (wid & 1) * 64, warpN = (wid >> 1) * 16;
    const uint32_t aoff = sb + (uint32_t)(warpM + (L & 7) + ((L >> 3) & 1) * 8) * 144
                        + ((L >> 4) & 1) * 16;
    const uint32_t boff = sb + 36864 + (uint32_t)(warpN + (L & 7)) * 144
                        + ((L >> 3) & 1) * 16;

    float acc[4][2][4];
#pragma unroll
    for (int mi = 0; mi < 4; ++mi)
#pragma unroll
        for (int ni = 0; ni < 2; ++ni)
#pragma unroll
            for (int r = 0; r < 4; ++r) acc[mi][ni][r] = 0.f;

    const int qb = z * qsplit;
    const int qe = min(qtotal, qb + qsplit);

    for (int q = qb; q < qe; ++q) {
        // ---- stage A: 64 fp32 -> bf16 hi/lo ----
        const float* ap;
        if (MODE == 0) ap = A + abase + q * 64 + ahalf * 32;
        else if (MODE == 1) {
            int ks = q * 2 + ahalf;
            ap = A + abase + ((oy + (ks >> 2)) * 20 + ox + (ks & 3)) * 32;
        } else {
            int ky = q / 3, kx = q - ky * 3;
            ap = A + abase + ((oy + ky) * 9 + ox + kx) * 64 + ahalf * 32;
        }
        {
            const float4* fp = (const float4*)ap;
            float4 v[8];
#pragma unroll
            for (int j = 0; j < 8; ++j) v[j] = fp[j];
            char* dh = smem + (size_t)arow * 144 + ahalf * 64;
            char* dl = dh + 18432;
#pragma unroll
            for (int j = 0; j < 4; ++j) {
                uint4 hh, ll;
                cvt8(v[2 * j], v[2 * j + 1], hh, ll);
                *(uint4*)(dh + j * 16) = hh;
                *(uint4*)(dl + j * 16) = ll;
            }
        }
        // ---- stage B: copy pre-split tile (64n x 64k hi + lo) ----
        {
            const char* bt = (const char*)(Bt + (((size_t)ntile * qtotal + q) << 10));
            const char* srch = bt + bcrow * 128 + bcseg * 32;
            char* dsth = smem + 36864 + (size_t)bcrow * 144 + bcseg * 32;
            *(uint4*)dsth = *(const uint4*)srch;
            *(uint4*)(dsth + 16) = *(const uint4*)(srch + 16);
            *(uint4*)(dsth + 9216) = *(const uint4*)(srch + 8192);
            *(uint4*)(dsth + 9216 + 16) = *(const uint4*)(srch + 8192 + 16);
        }
        __syncthreads();
        // ---- compute: 4 k16-steps, 24 mma each ----
#pragma unroll
        for (int ks4 = 0; ks4 < 4; ++ks4) {
            uint32_t ah[4][4], al[4][4], bh[2][2], bl[2][2];
#pragma unroll
            for (int mi = 0; mi < 4; ++mi) {
                ldsm4(aoff + mi * 2304 + ks4 * 32, ah[mi]);
                ldsm4(aoff + 18432 + mi * 2304 + ks4 * 32, al[mi]);
            }
#pragma unroll
            for (int ni = 0; ni < 2; ++ni) {
                ldsm2(boff + ni * 1152 + ks4 * 32, bh[ni]);
                ldsm2(boff + 9216 + ni * 1152 + ks4 * 32, bl[ni]);
            }
#pragma unroll
            for (int mi = 0; mi < 4; ++mi)
#pragma unroll
                for (int ni = 0; ni < 2; ++ni) {
                    mma16816(acc[mi][ni], ah[mi], bh[ni]);
                    mma16816(acc[mi][ni], ah[mi], bl[ni]);
                    mma16816(acc[mi][ni], al[mi], bh[ni]);
                }
        }
        __syncthreads();
    }

    // ---- epilogue ----
    const int gID = L >> 2, tg = L & 3;
#pragma unroll
    for (int mi = 0; mi < 4; ++mi) {
#pragma unroll
        for (int ni = 0; ni < 2; ++ni) {
            int m = mtile * 128 + warpM + mi * 16 + gID;
            int col = ntile * 64 + warpN + ni * 8 + tg * 2;
            float2 o0 = make_float2(acc[mi][ni][0], acc[mi][ni][1]);
            float2 o1 = make_float2(acc[mi][ni][2], acc[mi][ni][3]);
            if (bias) {
                float2 bb = *(const float2*)(bias + col);
                o0.x += bb.x; o0.y += bb.y; o1.x += bb.x; o1.y += bb.y;
            }
            if (dorelu) {
                o0.x = fmaxf(o0.x, 0.f); o0.y = fmaxf(o0.y, 0.f);
                o1.x = fmaxf(o1.x, 0.f); o1.y = fmaxf(o1.y, 0.f);
            }
            *(float2*)(C + (size_t)m * ldc + col) = o0;
            *(float2*)(C + (size_t)(m + 8) * ldc + col) = o1;
        }
    }
}

// ---------------- split-K reduce + bias + relu ----------------
__global__ void reduce_kernel(const float* __restrict__ bias, float* __restrict__ outp,
                              int N, int nparts, int stride, int count, int dorelu) {
    int i = blockIdx.x * blockDim.x + threadIdx.x;
    if (i >= count) return;
    float s = 0.f;
    for (int ss = 0; ss < nparts; ++ss) s += g_part[(size_t)ss * stride + i];
    s += bias[i % N];
    outp[i] = dorelu ? fmaxf(s, 0.f) : s;
}

// ---------------- wfeat = g_h @ Ww + bw ----------------
__global__ void __launch_bounds__(256) wfeat_kernel(const float* __restrict__ Ww,
                                                    const float* __restrict__ bw) {
    int t = blockIdx.x * 256 + threadIdx.x;
    int n = t >> 5, oc = t & 31;
    const float* hrow = g_h + (size_t)n * 512;
    float s = bw[oc];
#pragma unroll 8
    for (int k = 0; k < 512; ++k) s += hrow[k] * Ww[k * 32 + oc];
    g_wfeat[t] = s;
}

// ---------------- sequential scan ----------------
__global__ void __launch_bounds__(256) scan_kernel(const float* __restrict__ done,
                                                   const float* __restrict__ state0,
                                                   const int* __restrict__ position,
                                                   float* __restrict__ out_state) {
    const int b = blockIdx.x, cq = blockIdx.y * 8, j = threadIdx.x;
    float st[8];
#pragma unroll
    for (int c = 0; c < 8; ++c) st[c] = state0[b * 8192 + (cq + c) * 256 + j];
    for (int t = 0; t < 32; ++t) {
        int idx = t * 64 + b;
        float m = 1.0f - done[idx];
#pragma unroll
        for (int c = 0; c < 8; ++c) st[c] *= m;
        int p0 = position[idx * 2], p1 = position[idx * 2 + 1];
        if (j == p0 * 16 + p1) {
#pragma unroll
            for (int c = 0; c < 8; ++c) st[c] += g_wfeat[idx * 32 + cq + c];
        }
        float* hrow = g_hidden + (size_t)idx * 8256;
#pragma unroll
        for (int c = 0; c < 8; ++c) hrow[(cq + c) * 256 + j] = st[c];
    }
#pragma unroll
    for (int c = 0; c < 8; ++c) out_state[b * 8192 + (cq + c) * 256 + j] = st[c];
}

// ---------------- pos_net ----------------
__global__ void __launch_bounds__(64) posnet_kernel(const int* __restrict__ position,
                                                    const float* __restrict__ wp1,
                                                    const float* __restrict__ bp1,
                                                    const float* __restrict__ wp2,
                                                    const float* __restrict__ bp2) {
    __shared__ float hr[64];
    const int n = blockIdx.x, k = threadIdx.x;
    int p0 = position[n * 2], p1 = position[n * 2 + 1];
    hr[k] = fmaxf(wp1[p0 * 64 + k] + wp1[(16 + p1) * 64 + k] + bp1[k], 0.f);
    __syncthreads();
    float s = bp2[k];
#pragma unroll 8
    for (int j = 0; j < 64; ++j) s += hr[j] * wp2[j * 64 + k];
    g_hidden[(size_t)n * 8256 + 8192 + k] = s;
}

// ---------------- heads ----------------
__global__ void heads_kernel(const float* __restrict__ wpo2, const float* __restrict__ bpo2,
                             const float* __restrict__ wv2, const float* __restrict__ bv2,
                             float* __restrict__ out_logits, float* __restrict__ out_v) {
    int n = blockIdx.x * blockDim.x + threadIdx.x;
    if (n >= 2048) return;
    const float* z = g_z + (size_t)n * 128;
    float lg[5];
#pragma unroll
    for (int a = 0; a < 5; ++a) lg[a] = bpo2[a];
    float vv = bv2[0];
#pragma unroll 4
    for (int j = 0; j < 64; ++j) {
        float zj = z[j];
#pragma unroll
        for (int a = 0; a < 5; ++a) lg[a] += zj * wpo2[j * 5 + a];
        vv += z[64 + j] * wv2[j];
    }
#pragma unroll
    for (int a = 0; a < 5; ++a) out_logits[n * 5 + a] = lg[a];
    out_v[n] = vv;
}

// ---------------- launch ----------------
extern "C" void kernel_launch(void* const* d_in, const int* in_sizes, int n_in,
                              void* d_out, int out_size) {
    bool dict_order = (in_sizes[3] == 4096 && in_sizes[4] == 6144);
    int wb = dict_order ? 4 : 3;
    int posIdx = dict_order ? 3 : 25;

    const float* image  = (const float*)d_in[0];
    const float* done   = (const float*)d_in[1];
    const float* state0 = (const float*)d_in[2];
    const int*   position = (const int*)d_in[posIdx];
    const float* w1  = (const float*)d_in[wb + 0];
    const float* b1  = (const float*)d_in[wb + 1];
    const float* w2  = (const float*)d_in[wb + 2];
    const float* b2  = (const float*)d_in[wb + 3];
    const float* w3  = (const float*)d_in[wb + 4];
    const float* b3  = (const float*)d_in[wb + 5];
    const float* wfc = (const float*)d_in[wb + 6];
    const float* bfc = (const float*)d_in[wb + 7];
    const float* Ww  = (const float*)d_in[wb + 8];
    const float* bw  = (const float*)d_in[wb + 9];
    const float* wp1 = (const float*)d_in[wb + 10];
    const float* bp1 = (const float*)d_in[wb + 11];
    const float* wp2 = (const float*)d_in[wb + 12];
    const float* bp2 = (const float*)d_in[wb + 13];
    const float* wpo1 = (const float*)d_in[wb + 14];
    const float* bpo1 = (const float*)d_in[wb + 15];
    const float* wpo2 = (const float*)d_in[wb + 16];
    const float* bpo2 = (const float*)d_in[wb + 17];
    const float* wv1 = (const float*)d_in[wb + 18];
    const float* bv1 = (const float*)d_in[wb + 19];
    const float* wv2 = (const float*)d_in[wb + 20];
    const float* bv2 = (const float*)d_in[wb + 21];

    float* out = (float*)d_out;
    float* out_logits = out;
    float* out_v      = out + 10240;
    float* out_state  = out + 12288;

    float *p_a1, *p_a2, *p_a3, *p_h, *p_hidden, *p_part, *p_w1t, *p_bcat, *p_z;
    uint4 *p_w2sw, *p_w3sw, *p_wfcsw, *p_wposw;
    cudaGetSymbolAddress((void**)&p_a1, g_a1);
    cudaGetSymbolAddress((void**)&p_a2, g_a2);
    cudaGetSymbolAddress((void**)&p_a3, g_a3);
    cudaGetSymbolAddress((void**)&p_h, g_h);
    cudaGetSymbolAddress((void**)&p_hidden, g_hidden);
    cudaGetSymbolAddress((void**)&p_part, g_part);
    cudaGetSymbolAddress((void**)&p_w1t, g_w1t);
    cudaGetSymbolAddress((void**)&p_bcat, g_bcat);
    cudaGetSymbolAddress((void**)&p_z, g_z);
    cudaGetSymbolAddress((void**)&p_w2sw, g_w2sw);
    cudaGetSymbolAddress((void**)&p_w3sw, g_w3sw);
    cudaGetSymbolAddress((void**)&p_wfcsw, g_wfcsw);
    cudaGetSymbolAddress((void**)&p_wposw, g_wposw);

    const int MMSMEM = 55296;
    cudaFuncSetAttribute(conv1_kernel, cudaFuncAttributeMaxDynamicSharedMemorySize, 68928);
    cudaFuncSetAttribute(gemmMM<0>, cudaFuncAttributeMaxDynamicSharedMemorySize, MMSMEM);
    cudaFuncSetAttribute(gemmMM<1>, cudaFuncAttributeMaxDynamicSharedMemorySize, MMSMEM);
    cudaFuncSetAttribute(gemmMM<2>, cudaFuncAttributeMaxDynamicSharedMemorySize, MMSMEM);

    prep_kernel<<<3137, 512>>>(w1, w2, w3, wpo1, wv1, wfc, bpo1, bv1);
    conv1_kernel<<<4096, 256, 68928>>>(image, p_w1t, b1, p_a1);
    // conv2: M=165888, N=64, K=512 (8 chunks)
    gemmMM<1><<<dim3(1, 1296, 1), 256, MMSMEM>>>(p_a1, 0, p_w2sw, p_a2, 64,
                                                 8, 8, 165888, b2, 1);
    // conv3: M=100352, N=64, K=576 (9 chunks)
    gemmMM<2><<<dim3(1, 784, 1), 256, MMSMEM>>>(p_a2, 0, p_w3sw, p_a3, 64,
                                                9, 9, 100352, b3, 1);
    // FC: M=2048, N=512 (8 ntiles), K=3136 (49 chunks)
    gemmMM<0><<<dim3(8, 16, 1), 256, MMSMEM>>>(p_a3, 3136, p_wfcsw, p_h, 512,
                                               49, 49, 2048, bfc, 1);
    wfeat_kernel<<<256, 256>>>(Ww, bw);
    scan_kernel<<<dim3(64, 4, 1), 256>>>(done, state0, position, out_state);
    posnet_kernel<<<2048, 64>>>(position, wp1, bp1, wp2, bp2);
    // policy/value: M=2048, N=128 (2 ntiles), K=8256 (129 chunks), split-K=4
    gemmMM<0><<<dim3(2, 16, 4), 256, MMSMEM>>>(p_hidden, 8256, p_wposw, p_part, 128,
                                               33, 129, 2048, (const float*)0, 0);
    reduce_kernel<<<512, 512>>>(p_bcat, p_z, 128, 4, 2048 * 128, 2048 * 128, 1);
    heads_kernel<<<16, 128>>>(wpo2, bpo2, wv2, bv2, out_logits, out_v);
}

// round 8
// speedup vs baseline: 1.5641x; 1.0489x over previous
#include <cuda_runtime.h>
#include <cuda_bf16.h>
#include <cstdint>

typedef unsigned short ush;
typedef unsigned int uint32;

// ---------------- scratch (device globals; zero-initialized, no allocation) ----------------
__device__ ush g_imgh[2048 * 7056 * 4];   // image bf16 hi, 4-ch padded (c=3 stays 0)
__device__ ush g_imgl[2048 * 7056 * 4];
__device__ ush g_a1h[2048 * 400 * 32];    // conv1 out planes [n*400+p][32]
__device__ ush g_a1l[2048 * 400 * 32];
__device__ ush g_a2h[2048 * 81 * 64];     // conv2 out planes
__device__ ush g_a2l[2048 * 81 * 64];
__device__ ush g_a3h[2048 * 49 * 64];     // conv3 out planes [n*49+p][64] (k=p*64+c)
__device__ ush g_a3l[2048 * 49 * 64];
__device__ ush g_hidh[2048 * 8256];       // hidden planes [map 8192 | pos 64]
__device__ ush g_hidl[2048 * 8256];
__device__ float g_h[2048 * 512];         // CNN feature (fp32, feeds wfeat)
__device__ float g_wfeat[2048 * 32];
__device__ float g_part[4 * 2048 * 128];  // policy split-K partials
__device__ float g_z[2048 * 128];
__device__ float g_bcat[128];
// pre-split, pre-swizzled bf16 weight tiles. NT=64 tile: 16KB [hi 8K][lo 8K]; NT=32: 8KB.
__device__ uint4 g_w1sw[4 * 512];         // conv1: 4 chunks x 8KB
__device__ uint4 g_w2sw[8 * 1024];        // conv2: 8 chunks x 16KB
__device__ uint4 g_w3sw[9 * 1024];        // conv3: 9 chunks
__device__ uint4 g_wfcsw[8 * 49 * 1024];  // FC: 8 ntiles x 49 chunks
__device__ uint4 g_wposw[2 * 129 * 1024]; // policy: 2 ntiles x 129 chunks

// ---------------- helpers ----------------
static __device__ __forceinline__ uint32 s2u(const void* p) {
    uint32 a;
    asm("{ .reg .u64 t; cvta.to.shared.u64 t, %1; cvt.u32.u64 %0, t; }" : "=r"(a) : "l"(p));
    return a;
}
static __device__ __forceinline__ void cpa16(uint32 d, const void* s) {
    asm volatile("cp.async.cg.shared.global [%0], [%1], 16;" :: "r"(d), "l"(s));
}
static __device__ __forceinline__ void ldsm4(uint32 addr, uint32* r) {
    asm volatile("ldmatrix.sync.aligned.m8n8.x4.shared.b16 {%0,%1,%2,%3}, [%4];"
                 : "=r"(r[0]), "=r"(r[1]), "=r"(r[2]), "=r"(r[3]) : "r"(addr));
}
static __device__ __forceinline__ void ldsm2(uint32 addr, uint32* r) {
    asm volatile("ldmatrix.sync.aligned.m8n8.x2.shared.b16 {%0,%1}, [%2];"
                 : "=r"(r[0]), "=r"(r[1]) : "r"(addr));
}
static __device__ __forceinline__ void mma16816(float* c, const uint32* a, const uint32* b) {
    asm volatile(
        "mma.sync.aligned.m16n8k16.row.col.f32.bf16.bf16.f32 "
        "{%0,%1,%2,%3}, {%4,%5,%6,%7}, {%8,%9}, {%0,%1,%2,%3};"
        : "+f"(c[0]), "+f"(c[1]), "+f"(c[2]), "+f"(c[3])
        : "r"(a[0]), "r"(a[1]), "r"(a[2]), "r"(a[3]), "r"(b[0]), "r"(b[1]));
}
static __device__ __forceinline__ uint32 packsplit(float x0, float x1, uint32& lo) {
    __nv_bfloat16 h0 = __float2bfloat16_rn(x0), h1 = __float2bfloat16_rn(x1);
    __nv_bfloat16 l0 = __float2bfloat16_rn(x0 - __bfloat162float(h0));
    __nv_bfloat16 l1 = __float2bfloat16_rn(x1 - __bfloat162float(h1));
    lo = (uint32)__bfloat16_as_ushort(l0) | ((uint32)__bfloat16_as_ushort(l1) << 16);
    return (uint32)__bfloat16_as_ushort(h0) | ((uint32)__bfloat16_as_ushort(h1) << 16);
}

// ---------------- prep: weight split + swizzle into tiles ----------------
static __device__ __forceinline__ void wstore(uint4* tiles, int tilebytes, int tile,
                                              int nn, int kk, float v) {
    __nv_bfloat16 h = __float2bfloat16_rn(v);
    __nv_bfloat16 l = __float2bfloat16_rn(v - __bfloat162float(h));
    char* base = (char*)tiles + (size_t)tile * tilebytes;
    unsigned off = (unsigned)(nn * 128 + (((kk >> 3) ^ (nn & 7)) << 4) + (kk & 7) * 2);
    *(__nv_bfloat16*)(base + off) = h;
    *(__nv_bfloat16*)(base + tilebytes / 2 + off) = l;
}

__global__ void prep_kernel(const float* __restrict__ w1, const float* __restrict__ w2,
                            const float* __restrict__ w3, const float* __restrict__ wpo1,
                            const float* __restrict__ wv1, const float* __restrict__ wfc,
                            const float* __restrict__ bpo1, const float* __restrict__ bv1) {
    int i = blockIdx.x * blockDim.x + threadIdx.x;
    if (i < 6144) {  // conv1: w1[oc][c][ky][kx], k=(ky*8+kx)*4+c (pad c to 4)
        int oc = i / 192, r = i - oc * 192, c = r >> 6, ks = r & 63;
        int k = ks * 4 + c;
        wstore(g_w1sw, 8192, k >> 6, oc, k & 63, w1[i]);
    }
    if (i < 32768) { // conv2: w2[oc][c][ky][kx], k=(ky*4+kx)*32+c
        int oc = i >> 9, c = (i >> 4) & 31, ks = i & 15;
        int k = ks * 32 + c;
        wstore(g_w2sw, 16384, k >> 6, oc, k & 63, w2[i]);
    }
    if (i < 36864) { // conv3: k=(ky*3+kx)*64+c
        int oc = i / 576, r = i - oc * 576, c = r / 9, ks = r - c * 9;
        int k = ks * 64 + c;
        wstore(g_w3sw, 16384, k >> 6, oc, k & 63, w3[i]);
    }
    if (i < 8256 * 128) { // policy/value concat
        int k = i >> 7, n = i & 127;
        float v = (n < 64) ? wpo1[k * 64 + n] : wv1[k * 64 + n - 64];
        wstore(g_wposw, 16384, (n >> 6) * 129 + (k >> 6), n & 63, k & 63, v);
    }
    if (i < 3136 * 512) { // FC: k=p*64+c; src wfc[(c*49+p)][n]
        int k = i >> 9, n = i & 511;
        int p = k >> 6, c = k & 63;
        float v = wfc[(size_t)(c * 49 + p) * 512 + n];
        wstore(g_wfcsw, 16384, (n >> 6) * 49 + p, n & 63, c, v);
    }
    if (i < 128) g_bcat[i] = (i < 64) ? bpo1[i] : bv1[i - 64];
}

// ---------------- image -> padded bf16 hi/lo planes (fused /255) ----------------
__global__ void imgprep_kernel(const float* __restrict__ img) {
    size_t i = (size_t)blockIdx.x * 256 + threadIdx.x;   // pixel index
    if (i >= (size_t)2048 * 7056) return;
    const float* p = img + i * 3;
    float v[3] = {p[0] * (1.f / 255.f), p[1] * (1.f / 255.f), p[2] * (1.f / 255.f)};
    ushort4 h, l;
    ush* hp = &h.x; ush* lp = &l.x;
#pragma unroll
    for (int c = 0; c < 3; ++c) {
        __nv_bfloat16 hb = __float2bfloat16_rn(v[c]);
        hp[c] = __bfloat16_as_ushort(hb);
        lp[c] = __bfloat16_as_ushort(__float2bfloat16_rn(v[c] - __bfloat162float(hb)));
    }
    h.w = 0; l.w = 0;
    *(ushort4*)(g_imgh + i * 4) = h;
    *(ushort4*)(g_imgl + i * 4) = l;
}

// ---------------- pipelined mma.sync GEMM, bf16 hi/lo 3-MMA ----------------
// BM=128, BN=NT (64 or 32), BK=64 chunks, cp.async double buffer, swizzled smem.
// MODE 0: direct [gm][lda]; 1: conv2 gather; 2: conv3 gather; 3: conv1 gather.
template<int MODE, int NT>
__global__ void __launch_bounds__(256, 2) gemmP(
    const ush* __restrict__ Ah, const ush* __restrict__ Al, int lda,
    const uint4* __restrict__ Bt, int qtotal, int qsplit,
    float* __restrict__ Cf, ush* __restrict__ Ch, ush* __restrict__ Cl,
    int ldc, int Mtotal, const float* __restrict__ bias, int dorelu)
{
    constexpr int MI = (NT == 64) ? 4 : 2;
    constexpr int ABYTES = 32768;                // A hi 16K + A lo 16K
    constexpr int BBYTES = NT * 256;             // B hi + lo
    constexpr int BUFSZ = ABYTES + BBYTES;
    extern __shared__ __align__(16) char smem[];
    const uint32 sb = s2u(smem);
    const int tid = threadIdx.x;
    const int mtile = blockIdx.y, ntile = blockIdx.x, z = blockIdx.z;
    if (Cf) Cf += (size_t)z * Mtotal * ldc;

    // A gather mapping: thread = (row, half-of-64B)
    const int arow = tid & 127, ahalf = tid >> 7;
    const int gm = mtile * 128 + arow;
    size_t abase = 0; int oy = 0, ox = 0;
    if (MODE == 0) abase = (size_t)gm * lda;
    else if (MODE == 1) { int n = gm / 81, p = gm - n * 81; oy = (p / 9) * 2; ox = (p % 9) * 2; abase = (size_t)n * 12800; }
    else if (MODE == 2) { int n = gm / 49, p = gm - n * 49; oy = p / 7; ox = p - oy * 7; abase = (size_t)n * 5184; }
    else { int n = gm / 400, p = gm - n * 400; oy = p / 20; ox = p - oy * 20; abase = (size_t)n * 28224; }

    const int qb = z * qsplit;
    const int qe = min(qtotal, qb + qsplit);

    auto stage = [&](int q, int buf) {
        size_t off;
        if (MODE == 0) off = abase + (size_t)q * 64 + ahalf * 32;
        else if (MODE == 1) {
            int ks = q * 2 + ahalf;
            off = abase + (size_t)((oy + (ks >> 2)) * 20 + ox + (ks & 3)) * 32;
        } else if (MODE == 2) {
            int ky = q / 3, kx = q - ky * 3;
            off = abase + (size_t)((oy + ky) * 9 + ox + kx) * 64 + ahalf * 32;
        } else {
            int ky = q * 2 + ahalf;
            off = abase + (size_t)((oy * 4 + ky) * 84 + ox * 4) * 4;
        }
        uint32 Ab = sb + buf * BUFSZ;
        uint32 rowb = Ab + arow * 128;
        const char* gh = (const char*)(Ah + off);
        const char* gl = (const char*)(Al + off);
#pragma unroll
        for (int i = 0; i < 4; ++i) {
            int seg = ahalf * 4 + i;
            uint32 d = rowb + ((seg ^ (arow & 7)) << 4);
            cpa16(d, gh + i * 16);
            cpa16(d + 16384, gl + i * 16);
        }
        uint32 Bb = Ab + ABYTES;
        const uint4* bt = Bt + (size_t)(ntile * qtotal + q) * (BBYTES / 16);
#pragma unroll
        for (int i = 0; i < BBYTES / 16 / 256; ++i)
            cpa16(Bb + (tid + i * 256) * 16, bt + tid + i * 256);
        asm volatile("cp.async.commit_group;" ::: "memory");
    };

    const int wid = tid >> 5, L = tid & 31;
    const int warpM = (NT == 64) ? (wid & 1) * 64 : (wid & 3) * 32;
    const int warpN = (NT == 64) ? (wid >> 1) * 16 : (wid >> 2) * 16;
    const int arow0 = warpM + (L & 7) + ((L >> 3) & 1) * 8;
    const int asegh = (L >> 4) & 1;
    const int brow0 = warpN + (L & 7);
    const int bsegh = (L >> 3) & 1;

    float acc[MI][2][4];
#pragma unroll
    for (int mi = 0; mi < MI; ++mi)
#pragma unroll
        for (int ni = 0; ni < 2; ++ni)
#pragma unroll
            for (int r = 0; r < 4; ++r) acc[mi][ni][r] = 0.f;

    stage(qb, 0);
    for (int q = qb; q < qe; ++q) {
        int cb = (q - qb) & 1;
        if (q + 1 < qe) {
            stage(q + 1, cb ^ 1);
            asm volatile("cp.async.wait_group 1;" ::: "memory");
        } else {
            asm volatile("cp.async.wait_group 0;" ::: "memory");
        }
        __syncthreads();
        uint32 Ab = sb + cb * BUFSZ;
        uint32 Bb = Ab + ABYTES;
#pragma unroll
        for (int ks4 = 0; ks4 < 4; ++ks4) {
            uint32 ah[MI][4], al[MI][4], bh[2][2], bl[2][2];
#pragma unroll
            for (int mi = 0; mi < MI; ++mi) {
                int row = arow0 + mi * 16;
                int seg = ks4 * 2 + asegh;
                uint32 ad = Ab + row * 128 + ((seg ^ (row & 7)) << 4);
                ldsm4(ad, ah[mi]);
                ldsm4(ad + 16384, al[mi]);
            }
#pragma unroll
            for (int ni = 0; ni < 2; ++ni) {
                int row = brow0 + ni * 8;
                int seg = ks4 * 2 + bsegh;
                uint32 bd = Bb + row * 128 + ((seg ^ (row & 7)) << 4);
                ldsm2(bd, bh[ni]);
                ldsm2(bd + NT * 128, bl[ni]);
            }
#pragma unroll
            for (int mi = 0; mi < MI; ++mi)
#pragma unroll
                for (int ni = 0; ni < 2; ++ni) {
                    mma16816(acc[mi][ni], ah[mi], bh[ni]);
                    mma16816(acc[mi][ni], ah[mi], bl[ni]);
                    mma16816(acc[mi][ni], al[mi], bh[ni]);
                }
        }
        __syncthreads();
    }

    // ---- epilogue ----
    const int gID = L >> 2, tg = L & 3;
#pragma unroll
    for (int mi = 0; mi < MI; ++mi)
#pragma unroll
        for (int ni = 0; ni < 2; ++ni) {
            int m = mtile * 128 + warpM + mi * 16 + gID;
            int col = ntile * NT + warpN + ni * 8 + tg * 2;
            float x0 = acc[mi][ni][0], x1 = acc[mi][ni][1];
            float x2 = acc[mi][ni][2], x3 = acc[mi][ni][3];
            if (bias) {
                float2 bb = *(const float2*)(bias + col);
                x0 += bb.x; x1 += bb.y; x2 += bb.x; x3 += bb.y;
            }
            if (dorelu) {
                x0 = fmaxf(x0, 0.f); x1 = fmaxf(x1, 0.f);
                x2 = fmaxf(x2, 0.f); x3 = fmaxf(x3, 0.f);
            }
            if (Cf) {
                *(float2*)(Cf + (size_t)m * ldc + col) = make_float2(x0, x1);
                *(float2*)(Cf + (size_t)(m + 8) * ldc + col) = make_float2(x2, x3);
            } else {
                uint32 lo, hi;
                hi = packsplit(x0, x1, lo);
                *(uint32*)(Ch + (size_t)m * ldc + col) = hi;
                *(uint32*)(Cl + (size_t)m * ldc + col) = lo;
                hi = packsplit(x2, x3, lo);
                *(uint32*)(Ch + (size_t)(m + 8) * ldc + col) = hi;
                *(uint32*)(Cl + (size_t)(m + 8) * ldc + col) = lo;
            }
        }
}

// ---------------- split-K reduce + bias + relu ----------------
__global__ void reduce_kernel(float* __restrict__ outp, int N, int nparts, int stride,
                              int count, int dorelu) {
    int i = blockIdx.x * blockDim.x + threadIdx.x;
    if (i >= count) return;
    float s = 0.f;
    for (int ss = 0; ss < nparts; ++ss) s += g_part[(size_t)ss * stride + i];
    s += g_bcat[i % N];
    outp[i] = dorelu ? fmaxf(s, 0.f) : s;
}

// ---------------- wfeat = g_h @ Ww + bw ----------------
__global__ void __launch_bounds__(256) wfeat_kernel(const float* __restrict__ Ww,
                                                    const float* __restrict__ bw) {
    int t = blockIdx.x * 256 + threadIdx.x;
    int n = t >> 5, oc = t & 31;
    const float* hrow = g_h + (size_t)n * 512;
    float s = bw[oc];
#pragma unroll 8
    for (int k = 0; k < 512; ++k) s += hrow[k] * Ww[k * 32 + oc];
    g_wfeat[t] = s;
}

// ---------------- sequential scan: writes hidden planes + fp32 state ----------------
__global__ void __launch_bounds__(256) scan_kernel(const float* __restrict__ done,
                                                   const float* __restrict__ state0,
                                                   const int* __restrict__ position,
                                                   float* __restrict__ out_state) {
    const int b = blockIdx.x, cq = blockIdx.y * 8, j = threadIdx.x;
    float st[8];
#pragma unroll
    for (int c = 0; c < 8; ++c) st[c] = state0[b * 8192 + (cq + c) * 256 + j];
    for (int t = 0; t < 32; ++t) {
        int idx = t * 64 + b;
        float m = 1.0f - done[idx];
#pragma unroll
        for (int c = 0; c < 8; ++c) st[c] *= m;
        int p0 = position[idx * 2], p1 = position[idx * 2 + 1];
        if (j == p0 * 16 + p1) {
#pragma unroll
            for (int c = 0; c < 8; ++c) st[c] += g_wfeat[idx * 32 + cq + c];
        }
        size_t rb = (size_t)idx * 8256;
#pragma unroll
        for (int c = 0; c < 8; ++c) {
            __nv_bfloat16 h = __float2bfloat16_rn(st[c]);
            g_hidh[rb + (cq + c) * 256 + j] = __bfloat16_as_ushort(h);
            g_hidl[rb + (cq + c) * 256 + j] =
                __bfloat16_as_ushort(__float2bfloat16_rn(st[c] - __bfloat162float(h)));
        }
    }
#pragma unroll
    for (int c = 0; c < 8; ++c) out_state[b * 8192 + (cq + c) * 256 + j] = st[c];
}

// ---------------- pos_net -> hidden plane cols 8192..8255 ----------------
__global__ void __launch_bounds__(64) posnet_kernel(const int* __restrict__ position,
                                                    const float* __restrict__ wp1,
                                                    const float* __restrict__ bp1,
                                                    const float* __restrict__ wp2,
                                                    const float* __restrict__ bp2) {
    __shared__ float hr[64];
    const int n = blockIdx.x, k = threadIdx.x;
    int p0 = position[n * 2], p1 = position[n * 2 + 1];
    hr[k] = fmaxf(wp1[p0 * 64 + k] + wp1[(16 + p1) * 64 + k] + bp1[k], 0.f);
    __syncthreads();
    float s = bp2[k];
#pragma unroll 8
    for (int j = 0; j < 64; ++j) s += hr[j] * wp2[j * 64 + k];
    __nv_bfloat16 h = __float2bfloat16_rn(s);
    g_hidh[(size_t)n * 8256 + 8192 + k] = __bfloat16_as_ushort(h);
    g_hidl[(size_t)n * 8256 + 8192 + k] =
        __bfloat16_as_ushort(__float2bfloat16_rn(s - __bfloat162float(h)));
}

// ---------------- heads ----------------
__global__ void heads_kernel(const float* __restrict__ wpo2, const float* __restrict__ bpo2,
                             const float* __restrict__ wv2, const float* __restrict__ bv2,
                             float* __restrict__ out_logits, float* __restrict__ out_v) {
    int n = blockIdx.x * blockDim.x + threadIdx.x;
    if (n >= 2048) return;
    const float* z = g_z + (size_t)n * 128;
    float lg[5];
#pragma unroll
    for (int a = 0; a < 5; ++a) lg[a] = bpo2[a];
    float vv = bv2[0];
#pragma unroll 4
    for (int j = 0; j < 64; ++j) {
        float zj = z[j];
#pragma unroll
        for (int a = 0; a < 5; ++a) lg[a] += zj * wpo2[j * 5 + a];
        vv += z[64 + j] * wv2[j];
    }
#pragma unroll
    for (int a = 0; a < 5; ++a) out_logits[n * 5 + a] = lg[a];
    out_v[n] = vv;
}

// ---------------- launch ----------------
extern "C" void kernel_launch(void* const* d_in, const int* in_sizes, int n_in,
                              void* d_out, int out_size) {
    bool dict_order = (in_sizes[3] == 4096 && in_sizes[4] == 6144);
    int wb = dict_order ? 4 : 3;
    int posIdx = dict_order ? 3 : 25;

    const float* image  = (const float*)d_in[0];
    const float* done   = (const float*)d_in[1];
    const float* state0 = (const float*)d_in[2];
    const int*   position = (const int*)d_in[posIdx];
    const float* w1  = (const float*)d_in[wb + 0];
    const float* b1  = (const float*)d_in[wb + 1];
    const float* w2  = (const float*)d_in[wb + 2];
    const float* b2  = (const float*)d_in[wb + 3];
    const float* w3  = (const float*)d_in[wb + 4];
    const float* b3  = (const float*)d_in[wb + 5];
    const float* wfc = (const float*)d_in[wb + 6];
    const float* bfc = (const float*)d_in[wb + 7];
    const float* Ww  = (const float*)d_in[wb + 8];
    const float* bw  = (const float*)d_in[wb + 9];
    const float* wp1 = (const float*)d_in[wb + 10];
    const float* bp1 = (const float*)d_in[wb + 11];
    const float* wp2 = (const float*)d_in[wb + 12];
    const float* bp2 = (const float*)d_in[wb + 13];
    const float* wpo1 = (const float*)d_in[wb + 14];
    const float* bpo1 = (const float*)d_in[wb + 15];
    const float* wpo2 = (const float*)d_in[wb + 16];
    const float* bpo2 = (const float*)d_in[wb + 17];
    const float* wv1 = (const float*)d_in[wb + 18];
    const float* bv1 = (const float*)d_in[wb + 19];
    const float* wv2 = (const float*)d_in[wb + 20];
    const float* bv2 = (const float*)d_in[wb + 21];

    float* out = (float*)d_out;
    float* out_logits = out;
    float* out_v      = out + 10240;
    float* out_state  = out + 12288;

    ush *p_imgh, *p_imgl, *p_a1h, *p_a1l, *p_a2h, *p_a2l, *p_a3h, *p_a3l, *p_hidh, *p_hidl;
    float *p_h, *p_part, *p_z;
    uint4 *p_w1sw, *p_w2sw, *p_w3sw, *p_wfcsw, *p_wposw;
    cudaGetSymbolAddress((void**)&p_imgh, g_imgh);
    cudaGetSymbolAddress((void**)&p_imgl, g_imgl);
    cudaGetSymbolAddress((void**)&p_a1h, g_a1h);
    cudaGetSymbolAddress((void**)&p_a1l, g_a1l);
    cudaGetSymbolAddress((void**)&p_a2h, g_a2h);
    cudaGetSymbolAddress((void**)&p_a2l, g_a2l);
    cudaGetSymbolAddress((void**)&p_a3h, g_a3h);
    cudaGetSymbolAddress((void**)&p_a3l, g_a3l);
    cudaGetSymbolAddress((void**)&p_hidh, g_hidh);
    cudaGetSymbolAddress((void**)&p_hidl, g_hidl);
    cudaGetSymbolAddress((void**)&p_h, g_h);
    cudaGetSymbolAddress((void**)&p_part, g_part);
    cudaGetSymbolAddress((void**)&p_z, g_z);
    cudaGetSymbolAddress((void**)&p_w1sw, g_w1sw);
    cudaGetSymbolAddress((void**)&p_w2sw, g_w2sw);
    cudaGetSymbolAddress((void**)&p_w3sw, g_w3sw);
    cudaGetSymbolAddress((void**)&p_wfcsw, g_wfcsw);
    cudaGetSymbolAddress((void**)&p_wposw, g_wposw);

    const int SM64 = 2 * (32768 + 64 * 256);   // 98304
    const int SM32 = 2 * (32768 + 32 * 256);   // 81920
    cudaFuncSetAttribute(gemmP<3,32>, cudaFuncAttributeMaxDynamicSharedMemorySize, SM32);
    cudaFuncSetAttribute(gemmP<1,64>, cudaFuncAttributeMaxDynamicSharedMemorySize, SM64);
    cudaFuncSetAttribute(gemmP<2,64>, cudaFuncAttributeMaxDynamicSharedMemorySize, SM64);
    cudaFuncSetAttribute(gemmP<0,64>, cudaFuncAttributeMaxDynamicSharedMemorySize, SM64);

    prep_kernel<<<3137, 512>>>(w1, w2, w3, wpo1, wv1, wfc, bpo1, bv1);
    imgprep_kernel<<<56448, 256>>>(image);
    // conv1: M=2048*400=819200, N=32, K=256 (4 chunks)
    gemmP<3,32><<<dim3(1, 6400, 1), 256, SM32>>>(p_imgh, p_imgl, 0, p_w1sw, 4, 4,
                                                 (float*)0, p_a1h, p_a1l, 32, 819200, b1, 1);
    // conv2: M=165888, N=64, K=512 (8 chunks)
    gemmP<1,64><<<dim3(1, 1296, 1), 256, SM64>>>(p_a1h, p_a1l, 0, p_w2sw, 8, 8,
                                                 (float*)0, p_a2h, p_a2l, 64, 165888, b2, 1);
    // conv3: M=100352, N=64, K=576 (9 chunks)
    gemmP<2,64><<<dim3(1, 784, 1), 256, SM64>>>(p_a2h, p_a2l, 0, p_w3sw, 9, 9,
                                                (float*)0, p_a3h, p_a3l, 64, 100352, b3, 1);
    // FC: M=2048, N=512 (8 ntiles), K=3136 (49 chunks); fp32 out + bias + relu
    gemmP<0,64><<<dim3(8, 16, 1), 256, SM64>>>(p_a3h, p_a3l, 3136, p_wfcsw, 49, 49,
                                               p_h, (ush*)0, (ush*)0, 512, 2048, bfc, 1);
    wfeat_kernel<<<256, 256>>>(Ww, bw);
    scan_kernel<<<dim3(64, 4, 1), 256>>>(done, state0, position, out_state);
    posnet_kernel<<<2048, 64>>>(position, wp1, bp1, wp2, bp2);
    // policy/value: M=2048, N=128 (2 ntiles), K=8256 (129 chunks), split-K=4
    gemmP<0,64><<<dim3(2, 16, 4), 256, SM64>>>(p_hidh, p_hidl, 8256, p_wposw, 129, 33,
                                               p_part, (ush*)0, (ush*)0, 128, 2048,
                                               (const float*)0, 0);
    reduce_kernel<<<512, 512>>>(p_z, 128, 4, 2048 * 128, 2048 * 128, 1);
    heads_kernel<<<16, 128>>>(wpo2, bpo2, wv2, bv2, out_logits, out_v);
}

// round 9
// speedup vs baseline: 1.8371x; 1.1745x over previous
#include <cuda_runtime.h>
#include <cuda_bf16.h>
#include <cstdint>

typedef unsigned short ush;
typedef unsigned int uint32;

// ---------------- scratch (device globals; zero-initialized, no allocation) ----------------
__device__ ush g_imgh[2048 * 3 * 7056];   // image bf16 hi, planar [n][c][y*84+x]
__device__ ush g_imgl[2048 * 3 * 7056];
__device__ ush g_a1h[2048 * 400 * 32];    // conv1 out planes [n*400+p][32]
__device__ ush g_a1l[2048 * 400 * 32];
__device__ ush g_a2h[2048 * 81 * 64];     // conv2 out planes
__device__ ush g_a2l[2048 * 81 * 64];
__device__ ush g_a3h[2048 * 49 * 64];     // conv3 out planes [n*49+p][64] (k=p*64+c)
__device__ ush g_a3l[2048 * 49 * 64];
__device__ ush g_hidh[2048 * 8256];       // hidden planes [map 8192 | pos 64]
__device__ ush g_hidl[2048 * 8256];
__device__ float g_h[2048 * 512];         // CNN feature (fp32, feeds wfeat)
__device__ float g_wfeat[2048 * 32];
__device__ float g_part[2 * 2048 * 512];  // split-K partials (FC: 2x2048x512; policy: 8x2048x128)
__device__ float g_z[2048 * 128];
__device__ float g_bcat[128];
// pre-split, pre-swizzled bf16 weight tiles. NT=64 tile: 16KB [hi 8K][lo 8K]; NT=32: 8KB.
__device__ uint4 g_w1sw[3 * 512];         // conv1: 3 chunks x 8KB
__device__ uint4 g_w2sw[8 * 1024];        // conv2: 8 chunks x 16KB
__device__ uint4 g_w3sw[9 * 1024];        // conv3: 9 chunks
__device__ uint4 g_wfcsw[8 * 49 * 1024];  // FC: 8 ntiles x 49 chunks
__device__ uint4 g_wposw[2 * 129 * 1024]; // policy: 2 ntiles x 129 chunks

// ---------------- helpers ----------------
static __device__ __forceinline__ uint32 s2u(const void* p) {
    uint32 a;
    asm("{ .reg .u64 t; cvta.to.shared.u64 t, %1; cvt.u32.u64 %0, t; }" : "=r"(a) : "l"(p));
    return a;
}
static __device__ __forceinline__ void cpa16(uint32 d, const void* s) {
    asm volatile("cp.async.cg.shared.global [%0], [%1], 16;" :: "r"(d), "l"(s));
}
static __device__ __forceinline__ void cpa8(uint32 d, const void* s) {
    asm volatile("cp.async.ca.shared.global [%0], [%1], 8;" :: "r"(d), "l"(s));
}
static __device__ __forceinline__ void ldsm4(uint32 addr, uint32* r) {
    asm volatile("ldmatrix.sync.aligned.m8n8.x4.shared.b16 {%0,%1,%2,%3}, [%4];"
                 : "=r"(r[0]), "=r"(r[1]), "=r"(r[2]), "=r"(r[3]) : "r"(addr));
}
static __device__ __forceinline__ void ldsm2(uint32 addr, uint32* r) {
    asm volatile("ldmatrix.sync.aligned.m8n8.x2.shared.b16 {%0,%1}, [%2];"
                 : "=r"(r[0]), "=r"(r[1]) : "r"(addr));
}
static __device__ __forceinline__ void mma16816(float* c, const uint32* a, const uint32* b) {
    asm volatile(
        "mma.sync.aligned.m16n8k16.row.col.f32.bf16.bf16.f32 "
        "{%0,%1,%2,%3}, {%4,%5,%6,%7}, {%8,%9}, {%0,%1,%2,%3};"
        : "+f"(c[0]), "+f"(c[1]), "+f"(c[2]), "+f"(c[3])
        : "r"(a[0]), "r"(a[1]), "r"(a[2]), "r"(a[3]), "r"(b[0]), "r"(b[1]));
}
static __device__ __forceinline__ uint32 packsplit(float x0, float x1, uint32& lo) {
    __nv_bfloat16 h0 = __float2bfloat16_rn(x0), h1 = __float2bfloat16_rn(x1);
    __nv_bfloat16 l0 = __float2bfloat16_rn(x0 - __bfloat162float(h0));
    __nv_bfloat16 l1 = __float2bfloat16_rn(x1 - __bfloat162float(h1));
    lo = (uint32)__bfloat16_as_ushort(l0) | ((uint32)__bfloat16_as_ushort(l1) << 16);
    return (uint32)__bfloat16_as_ushort(h0) | ((uint32)__bfloat16_as_ushort(h1) << 16);
}

// ---------------- prep: weight split + swizzle into tiles ----------------
static __device__ __forceinline__ void wstore(uint4* tiles, int tilebytes, int tile,
                                              int nn, int kk, float v) {
    __nv_bfloat16 h = __float2bfloat16_rn(v);
    __nv_bfloat16 l = __float2bfloat16_rn(v - __bfloat162float(h));
    char* base = (char*)tiles + (size_t)tile * tilebytes;
    unsigned off = (unsigned)(nn * 128 + (((kk >> 3) ^ (nn & 7)) << 4) + (kk & 7) * 2);
    *(__nv_bfloat16*)(base + off) = h;
    *(__nv_bfloat16*)(base + tilebytes / 2 + off) = l;
}

__global__ void prep_kernel(const float* __restrict__ w1, const float* __restrict__ w2,
                            const float* __restrict__ w3, const float* __restrict__ wpo1,
                            const float* __restrict__ wv1, const float* __restrict__ wfc,
                            const float* __restrict__ bpo1, const float* __restrict__ bv1) {
    int i = blockIdx.x * blockDim.x + threadIdx.x;
    if (i < 6144) {  // conv1: w1[oc][c][ky][kx], k = c*64 + (ky*8+kx)  (channel-major)
        int oc = i / 192, r = i - oc * 192;            // r = c*64 + ks
        wstore(g_w1sw, 8192, r >> 6, oc, r & 63, w1[i]);
    }
    if (i < 32768) { // conv2: w2[oc][c][ky][kx], k=(ky*4+kx)*32+c
        int oc = i >> 9, c = (i >> 4) & 31, ks = i & 15;
        int k = ks * 32 + c;
        wstore(g_w2sw, 16384, k >> 6, oc, k & 63, w2[i]);
    }
    if (i < 36864) { // conv3: k=(ky*3+kx)*64+c
        int oc = i / 576, r = i - oc * 576, c = r / 9, ks = r - c * 9;
        int k = ks * 64 + c;
        wstore(g_w3sw, 16384, k >> 6, oc, k & 63, w3[i]);
    }
    if (i < 8256 * 128) { // policy/value concat
        int k = i >> 7, n = i & 127;
        float v = (n < 64) ? wpo1[k * 64 + n] : wv1[k * 64 + n - 64];
        wstore(g_wposw, 16384, (n >> 6) * 129 + (k >> 6), n & 63, k & 63, v);
    }
    if (i < 3136 * 512) { // FC: k=p*64+c; src wfc[(c*49+p)][n]
        int k = i >> 9, n = i & 511;
        int p = k >> 6, c = k & 63;
        float v = wfc[(size_t)(c * 49 + p) * 512 + n];
        wstore(g_wfcsw, 16384, (n >> 6) * 49 + p, n & 63, c, v);
    }
    if (i < 128) g_bcat[i] = (i < 64) ? bpo1[i] : bv1[i - 64];
}

// ---------------- image -> planar bf16 hi/lo (fused /255) ----------------
__global__ void imgprep_kernel(const float* __restrict__ img) {
    size_t i = (size_t)blockIdx.x * 256 + threadIdx.x;   // pixel index
    if (i >= (size_t)2048 * 7056) return;
    size_t n = i / 7056, pix = i - n * 7056;
    const float* p = img + i * 3;
#pragma unroll
    for (int c = 0; c < 3; ++c) {
        float v = p[c] * (1.f / 255.f);
        __nv_bfloat16 hb = __float2bfloat16_rn(v);
        size_t o = (n * 3 + c) * 7056 + pix;
        g_imgh[o] = __bfloat16_as_ushort(hb);
        g_imgl[o] = __bfloat16_as_ushort(__float2bfloat16_rn(v - __bfloat162float(hb)));
    }
}

// ---------------- pipelined mma.sync GEMM, bf16 hi/lo 3-MMA ----------------
// BM=128, BN=NT, BK=64 chunks, cp.async double buffer, swizzled smem.
// MODE 0: direct [gm][lda]; 1: conv2 gather; 2: conv3 gather; 3: conv1 planar gather.
template<int MODE, int NT>
__global__ void __launch_bounds__(256, 2) gemmP(
    const ush* __restrict__ Ah, const ush* __restrict__ Al, int lda,
    const uint4* __restrict__ Bt, int qtotal, int qsplit,
    float* __restrict__ Cf, ush* __restrict__ Ch, ush* __restrict__ Cl,
    int ldc, int Mtotal, const float* __restrict__ bias, int dorelu)
{
    constexpr int MI = (NT == 64) ? 4 : 2;
    constexpr int ABYTES = 32768;                // A hi 16K + A lo 16K
    constexpr int BBYTES = NT * 256;             // B hi + lo
    constexpr int BUFSZ = ABYTES + BBYTES;
    extern __shared__ __align__(16) char smem[];
    const uint32 sb = s2u(smem);
    const int tid = threadIdx.x;
    const int mtile = blockIdx.y, ntile = blockIdx.x, z = blockIdx.z;
    if (Cf) Cf += (size_t)z * Mtotal * ldc;

    // A gather mapping: thread = (row, half-of-64B)
    const int arow = tid & 127, ahalf = tid >> 7;
    const int gm = mtile * 128 + arow;
    size_t abase = 0; int oy = 0, ox = 0;
    if (MODE == 0) abase = (size_t)gm * lda;
    else if (MODE == 1) { int n = gm / 81, p = gm - n * 81; oy = (p / 9) * 2; ox = (p % 9) * 2; abase = (size_t)n * 12800; }
    else if (MODE == 2) { int n = gm / 49, p = gm - n * 49; oy = p / 7; ox = p - oy * 7; abase = (size_t)n * 5184; }
    else { int n = gm / 400, p = gm - n * 400; oy = p / 20; ox = p - oy * 20; abase = (size_t)n * 21168; }

    const int qb = z * qsplit;
    const int qe = min(qtotal, qb + qsplit);

    auto stage = [&](int q, int buf) {
        uint32 Ab = sb + buf * BUFSZ;
        uint32 rowb = Ab + arow * 128;
        if (MODE == 3) {
            // planar: q = channel; 4 ky rows of 8 pixels each (16B), 8B-aligned src
            size_t base = abase + (size_t)q * 7056 + (size_t)(oy * 4) * 84 + ox * 4;
#pragma unroll
            for (int i = 0; i < 4; ++i) {
                int ky = ahalf * 4 + i;
                const char* gh = (const char*)(Ah + base + ky * 84);
                const char* gl = (const char*)(Al + base + ky * 84);
                uint32 d = rowb + ((ky ^ (arow & 7)) << 4);
                cpa8(d, gh); cpa8(d + 8, gh + 8);
                cpa8(d + 16384, gl); cpa8(d + 16384 + 8, gl + 8);
            }
        } else {
            size_t off;
            if (MODE == 0) off = abase + (size_t)q * 64 + ahalf * 32;
            else if (MODE == 1) {
                int ks = q * 2 + ahalf;
                off = abase + (size_t)((oy + (ks >> 2)) * 20 + ox + (ks & 3)) * 32;
            } else {
                int ky = q / 3, kx = q - ky * 3;
                off = abase + (size_t)((oy + ky) * 9 + ox + kx) * 64 + ahalf * 32;
            }
            const char* gh = (const char*)(Ah + off);
            const char* gl = (const char*)(Al + off);
#pragma unroll
            for (int i = 0; i < 4; ++i) {
                int seg = ahalf * 4 + i;
                uint32 d = rowb + ((seg ^ (arow & 7)) << 4);
                cpa16(d, gh + i * 16);
                cpa16(d + 16384, gl + i * 16);
            }
        }
        uint32 Bb = Ab + ABYTES;
        const uint4* bt = Bt + (size_t)(ntile * qtotal + q) * (BBYTES / 16);
#pragma unroll
        for (int i = 0; i < BBYTES / 16 / 256; ++i)
            cpa16(Bb + (tid + i * 256) * 16, bt + tid + i * 256);
        asm volatile("cp.async.commit_group;" ::: "memory");
    };

    const int wid = tid >> 5, L = tid & 31;
    const int warpM = (NT == 64) ? (wid & 1) * 64 : (wid & 3) * 32;
    const int warpN = (NT == 64) ? (wid >> 1) * 16 : (wid >> 2) * 16;
    const int arow0 = warpM + (L & 7) + ((L >> 3) & 1) * 8;
    const int asegh = (L >> 4) & 1;
    const int brow0 = warpN + (L & 7);
    const int bsegh = (L >> 3) & 1;

    float acc[MI][2][4];
#pragma unroll
    for (int mi = 0; mi < MI; ++mi)
#pragma unroll
        for (int ni = 0; ni < 2; ++ni)
#pragma unroll
            for (int r = 0; r < 4; ++r) acc[mi][ni][r] = 0.f;

    stage(qb, 0);
    for (int q = qb; q < qe; ++q) {
        int cb = (q - qb) & 1;
        if (q + 1 < qe) {
            stage(q + 1, cb ^ 1);
            asm volatile("cp.async.wait_group 1;" ::: "memory");
        } else {
            asm volatile("cp.async.wait_group 0;" ::: "memory");
        }
        __syncthreads();
        uint32 Ab = sb + cb * BUFSZ;
        uint32 Bb = Ab + ABYTES;
#pragma unroll
        for (int ks4 = 0; ks4 < 4; ++ks4) {
            uint32 ah[MI][4], al[MI][4], bh[2][2], bl[2][2];
#pragma unroll
            for (int mi = 0; mi < MI; ++mi) {
                int row = arow0 + mi * 16;
                int seg = ks4 * 2 + asegh;
                uint32 ad = Ab + row * 128 + ((seg ^ (row & 7)) << 4);
                ldsm4(ad, ah[mi]);
                ldsm4(ad + 16384, al[mi]);
            }
#pragma unroll
            for (int ni = 0; ni < 2; ++ni) {
                int row = brow0 + ni * 8;
                int seg = ks4 * 2 + bsegh;
                uint32 bd = Bb + row * 128 + ((seg ^ (row & 7)) << 4);
                ldsm2(bd, bh[ni]);
                ldsm2(bd + NT * 128, bl[ni]);
            }
#pragma unroll
            for (int mi = 0; mi < MI; ++mi)
#pragma unroll
                for (int ni = 0; ni < 2; ++ni) {
                    mma16816(acc[mi][ni], ah[mi], bh[ni]);
                    mma16816(acc[mi][ni], ah[mi], bl[ni]);
                    mma16816(acc[mi][ni], al[mi], bh[ni]);
                }
        }
        __syncthreads();
    }

    // ---- epilogue ----
    const int gID = L >> 2, tg = L & 3;
#pragma unroll
    for (int mi = 0; mi < MI; ++mi)
#pragma unroll
        for (int ni = 0; ni < 2; ++ni) {
            int m = mtile * 128 + warpM + mi * 16 + gID;
            int col = ntile * NT + warpN + ni * 8 + tg * 2;
            float x0 = acc[mi][ni][0], x1 = acc[mi][ni][1];
            float x2 = acc[mi][ni][2], x3 = acc[mi][ni][3];
            if (bias) {
                float2 bb = *(const float2*)(bias + col);
                x0 += bb.x; x1 += bb.y; x2 += bb.x; x3 += bb.y;
            }
            if (dorelu) {
                x0 = fmaxf(x0, 0.f); x1 = fmaxf(x1, 0.f);
                x2 = fmaxf(x2, 0.f); x3 = fmaxf(x3, 0.f);
            }
            if (Cf) {
                *(float2*)(Cf + (size_t)m * ldc + col) = make_float2(x0, x1);
                *(float2*)(Cf + (size_t)(m + 8) * ldc + col) = make_float2(x2, x3);
            } else {
                uint32 lo, hi;
                hi = packsplit(x0, x1, lo);
                *(uint32*)(Ch + (size_t)m * ldc + col) = hi;
                *(uint32*)(Cl + (size_t)m * ldc + col) = lo;
                hi = packsplit(x2, x3, lo);
                *(uint32*)(Ch + (size_t)(m + 8) * ldc + col) = hi;
                *(uint32*)(Cl + (size_t)(m + 8) * ldc + col) = lo;
            }
        }
}

// ---------------- split-K reduce + bias + relu ----------------
__global__ void reduce_kernel(const float* __restrict__ bias, float* __restrict__ outp,
                              int N, int nparts, int stride, int count, int dorelu) {
    int i = blockIdx.x * blockDim.x + threadIdx.x;
    if (i >= count) return;
    float s = 0.f;
    for (int ss = 0; ss < nparts; ++ss) s += g_part[(size_t)ss * stride + i];
    s += bias[i % N];
    outp[i] = dorelu ? fmaxf(s, 0.f) : s;
}

// ---------------- wfeat = g_h @ Ww + bw ----------------
__global__ void __launch_bounds__(256) wfeat_kernel(const float* __restrict__ Ww,
                                                    const float* __restrict__ bw) {
    int t = blockIdx.x * 256 + threadIdx.x;
    int n = t >> 5, oc = t & 31;
    const float* hrow = g_h + (size_t)n * 512;
    float s = bw[oc];
#pragma unroll 8
    for (int k = 0; k < 512; ++k) s += hrow[k] * Ww[k * 32 + oc];
    g_wfeat[t] = s;
}

// ---------------- sequential scan: writes hidden planes + fp32 state ----------------
__global__ void __launch_bounds__(256) scan_kernel(const float* __restrict__ done,
                                                   const float* __restrict__ state0,
                                                   const int* __restrict__ position,
                                                   float* __restrict__ out_state) {
    const int b = blockIdx.x, cq = blockIdx.y * 8, j = threadIdx.x;
    float st[8];
#pragma unroll
    for (int c = 0; c < 8; ++c) st[c] = state0[b * 8192 + (cq + c) * 256 + j];
    for (int t = 0; t < 32; ++t) {
        int idx = t * 64 + b;
        float m = 1.0f - done[idx];
#pragma unroll
        for (int c = 0; c < 8; ++c) st[c] *= m;
        int p0 = position[idx * 2], p1 = position[idx * 2 + 1];
        if (j == p0 * 16 + p1) {
#pragma unroll
            for (int c = 0; c < 8; ++c) st[c] += g_wfeat[idx * 32 + cq + c];
        }
        size_t rb = (size_t)idx * 8256;
#pragma unroll
        for (int c = 0; c < 8; ++c) {
            __nv_bfloat16 h = __float2bfloat16_rn(st[c]);
            g_hidh[rb + (cq + c) * 256 + j] = __bfloat16_as_ushort(h);
            g_hidl[rb + (cq + c) * 256 + j] =
                __bfloat16_as_ushort(__float2bfloat16_rn(st[c] - __bfloat162float(h)));
        }
    }
#pragma unroll
    for (int c = 0; c < 8; ++c) out_state[b * 8192 + (cq + c) * 256 + j] = st[c];
}

// ---------------- pos_net -> hidden plane cols 8192..8255 ----------------
__global__ void __launch_bounds__(64) posnet_kernel(const int* __restrict__ position,
                                                    const float* __restrict__ wp1,
                                                    const float* __restrict__ bp1,
                                                    const float* __restrict__ wp2,
                                                    const float* __restrict__ bp2) {
    __shared__ float hr[64];
    const int n = blockIdx.x, k = threadIdx.x;
    int p0 = position[n * 2], p1 = position[n * 2 + 1];
    hr[k] = fmaxf(wp1[p0 * 64 + k] + wp1[(16 + p1) * 64 + k] + bp1[k], 0.f);
    __syncthreads();
    float s = bp2[k];
#pragma unroll 8
    for (int j = 0; j < 64; ++j) s += hr[j] * wp2[j * 64 + k];
    __nv_bfloat16 h = __float2bfloat16_rn(s);
    g_hidh[(size_t)n * 8256 + 8192 + k] = __bfloat16_as_ushort(h);
    g_hidl[(size_t)n * 8256 + 8192 + k] =
        __bfloat16_as_ushort(__float2bfloat16_rn(s - __bfloat162float(h)));
}

// ---------------- heads ----------------
__global__ void heads_kernel(const float* __restrict__ wpo2, const float* __restrict__ bpo2,
                             const float* __restrict__ wv2, const float* __restrict__ bv2,
                             float* __restrict__ out_logits, float* __restrict__ out_v) {
    int n = blockIdx.x * blockDim.x + threadIdx.x;
    if (n >= 2048) return;
    const float* z = g_z + (size_t)n * 128;
    float lg[5];
#pragma unroll
    for (int a = 0; a < 5; ++a) lg[a] = bpo2[a];
    float vv = bv2[0];
#pragma unroll 4
    for (int j = 0; j < 64; ++j) {
        float zj = z[j];
#pragma unroll
        for (int a = 0; a < 5; ++a) lg[a] += zj * wpo2[j * 5 + a];
        vv += z[64 + j] * wv2[j];
    }
#pragma unroll
    for (int a = 0; a < 5; ++a) out_logits[n * 5 + a] = lg[a];
    out_v[n] = vv;
}

// ---------------- launch ----------------
extern "C" void kernel_launch(void* const* d_in, const int* in_sizes, int n_in,
                              void* d_out, int out_size) {
    bool dict_order = (in_sizes[3] == 4096 && in_sizes[4] == 6144);
    int wb = dict_order ? 4 : 3;
    int posIdx = dict_order ? 3 : 25;

    const float* image  = (const float*)d_in[0];
    const float* done   = (const float*)d_in[1];
    const float* state0 = (const float*)d_in[2];
    const int*   position = (const int*)d_in[posIdx];
    const float* w1  = (const float*)d_in[wb + 0];
    const float* b1  = (const float*)d_in[wb + 1];
    const float* w2  = (const float*)d_in[wb + 2];
    const float* b2  = (const float*)d_in[wb + 3];
    const float* w3  = (const float*)d_in[wb + 4];
    const float* b3  = (const float*)d_in[wb + 5];
    const float* wfc = (const float*)d_in[wb + 6];
    const float* bfc = (const float*)d_in[wb + 7];
    const float* Ww  = (const float*)d_in[wb + 8];
    const float* bw  = (const float*)d_in[wb + 9];
    const float* wp1 = (const float*)d_in[wb + 10];
    const float* bp1 = (const float*)d_in[wb + 11];
    const float* wp2 = (const float*)d_in[wb + 12];
    const float* bp2 = (const float*)d_in[wb + 13];
    const float* wpo1 = (const float*)d_in[wb + 14];
    const float* bpo1 = (const float*)d_in[wb + 15];
    const float* wpo2 = (const float*)d_in[wb + 16];
    const float* bpo2 = (const float*)d_in[wb + 17];
    const float* wv1 = (const float*)d_in[wb + 18];
    const float* bv1 = (const float*)d_in[wb + 19];
    const float* wv2 = (const float*)d_in[wb + 20];
    const float* bv2 = (const float*)d_in[wb + 21];

    float* out = (float*)d_out;
    float* out_logits = out;
    float* out_v      = out + 10240;
    float* out_state  = out + 12288;

    ush *p_imgh, *p_imgl, *p_a1h, *p_a1l, *p_a2h, *p_a2l, *p_a3h, *p_a3l, *p_hidh, *p_hidl;
    float *p_h, *p_part, *p_z, *p_bcat;
    uint4 *p_w1sw, *p_w2sw, *p_w3sw, *p_wfcsw, *p_wposw;
    cudaGetSymbolAddress((void**)&p_imgh, g_imgh);
    cudaGetSymbolAddress((void**)&p_imgl, g_imgl);
    cudaGetSymbolAddress((void**)&p_a1h, g_a1h);
    cudaGetSymbolAddress((void**)&p_a1l, g_a1l);
    cudaGetSymbolAddress((void**)&p_a2h, g_a2h);
    cudaGetSymbolAddress((void**)&p_a2l, g_a2l);
    cudaGetSymbolAddress((void**)&p_a3h, g_a3h);
    cudaGetSymbolAddress((void**)&p_a3l, g_a3l);
    cudaGetSymbolAddress((void**)&p_hidh, g_hidh);
    cudaGetSymbolAddress((void**)&p_hidl, g_hidl);
    cudaGetSymbolAddress((void**)&p_h, g_h);
    cudaGetSymbolAddress((void**)&p_part, g_part);
    cudaGetSymbolAddress((void**)&p_z, g_z);
    cudaGetSymbolAddress((void**)&p_bcat, g_bcat);
    cudaGetSymbolAddress((void**)&p_w1sw, g_w1sw);
    cudaGetSymbolAddress((void**)&p_w2sw, g_w2sw);
    cudaGetSymbolAddress((void**)&p_w3sw, g_w3sw);
    cudaGetSymbolAddress((void**)&p_wfcsw, g_wfcsw);
    cudaGetSymbolAddress((void**)&p_wposw, g_wposw);

    const int SM64 = 2 * (32768 + 64 * 256);   // 98304
    const int SM32 = 2 * (32768 + 32 * 256);   // 81920
    cudaFuncSetAttribute(gemmP<3,32>, cudaFuncAttributeMaxDynamicSharedMemorySize, SM32);
    cudaFuncSetAttribute(gemmP<1,64>, cudaFuncAttributeMaxDynamicSharedMemorySize, SM64);
    cudaFuncSetAttribute(gemmP<2,64>, cudaFuncAttributeMaxDynamicSharedMemorySize, SM64);
    cudaFuncSetAttribute(gemmP<0,64>, cudaFuncAttributeMaxDynamicSharedMemorySize, SM64);

    prep_kernel<<<3137, 512>>>(w1, w2, w3, wpo1, wv1, wfc, bpo1, bv1);
    imgprep_kernel<<<56448, 256>>>(image);
    // conv1: M=819200, N=32, K=192 (3 chunks, channel-planar)
    gemmP<3,32><<<dim3(1, 6400, 1), 256, SM32>>>(p_imgh, p_imgl, 0, p_w1sw, 3, 3,
                                                 (float*)0, p_a1h, p_a1l, 32, 819200, b1, 1);
    // conv2: M=165888, N=64, K=512 (8 chunks)
    gemmP<1,64><<<dim3(1, 1296, 1), 256, SM64>>>(p_a1h, p_a1l, 0, p_w2sw, 8, 8,
                                                 (float*)0, p_a2h, p_a2l, 64, 165888, b2, 1);
    // conv3: M=100352, N=64, K=576 (9 chunks)
    gemmP<2,64><<<dim3(1, 784, 1), 256, SM64>>>(p_a2h, p_a2l, 0, p_w3sw, 9, 9,
                                                (float*)0, p_a3h, p_a3l, 64, 100352, b3, 1);
    // FC: M=2048, N=512 (8 ntiles), K=3136 (49 chunks), split-K=2
    gemmP<0,64><<<dim3(8, 16, 2), 256, SM64>>>(p_a3h, p_a3l, 3136, p_wfcsw, 49, 25,
                                               p_part, (ush*)0, (ush*)0, 512, 2048,
                                               (const float*)0, 0);
    reduce_kernel<<<2048, 512>>>(bfc, p_h, 512, 2, 2048 * 512, 2048 * 512, 1);
    wfeat_kernel<<<256, 256>>>(Ww, bw);
    scan_kernel<<<dim3(64, 4, 1), 256>>>(done, state0, position, out_state);
    posnet_kernel<<<2048, 64>>>(position, wp1, bp1, wp2, bp2);
    // policy/value: M=2048, N=128 (2 ntiles), K=8256 (129 chunks), split-K=8
    gemmP<0,64><<<dim3(2, 16, 8), 256, SM64>>>(p_hidh, p_hidl, 8256, p_wposw, 129, 17,
                                               p_part, (ush*)0, (ush*)0, 128, 2048,
                                               (const float*)0, 0);
    reduce_kernel<<<512, 512>>>(p_bcat, p_z, 128, 8, 2048 * 128, 2048 * 128, 1);
    heads_kernel<<<16, 128>>>(wpo2, bpo2, wv2, bv2, out_logits, out_v);
}